// round 13
// baseline (speedup 1.0000x reference)
#include <cuda_runtime.h>
#include <cuda_bf16.h>
#include <cuda_fp16.h>
#include <math.h>
#include <stdint.h>

#define B_   2
#define T_   1024
#define C_   1024
#define H_   16
#define HD_  64
#define L_   2
#define E_   8
#define FF_  4096
#define V_   32000
#define NTOK (B_ * T_)
#define CAP  320   // ceil(1.25 * 2048 / 8); 320 = 5 * 64 -> exact 64-row tiling

// ---------------- scratch (static device globals; no allocations) ----------------
__device__ float g_x[NTOK * C_];
__device__ float g_ln[NTOK * C_];
__device__ float g_qkv[NTOK * 3 * C_];
__device__ float g_attn[NTOK * C_];
__device__ float g_gates[NTOK * E_];
__device__ int   g_top[NTOK * 2];
__device__ int   g_slot[NTOK * 2];
__device__ float g_buf [E_ * CAP * C_];
__device__ float g_hbuf[E_ * CAP * FF_];
__device__ float g_ybuf[E_ * CAP * C_];

// ---------------- helpers ----------------
__device__ __forceinline__ float warp_sum(float v) {
#pragma unroll
    for (int o = 16; o; o >>= 1) v += __shfl_xor_sync(0xffffffffu, v, o);
    return v;
}
__device__ __forceinline__ float gelu_exact(float v) {
    return 0.5f * v * (1.0f + erff(v * 0.70710678118654752f));
}
__device__ __forceinline__ float to_tf32(float v) {
    float o; asm("cvt.rna.tf32.f32 %0, %1;" : "=f"(o) : "f"(v)); return o;
}
__device__ __forceinline__ float bf_hi(float v) {
    return __bfloat162float(__float2bfloat16(v));
}
__device__ __forceinline__ uint32_t pack_bf2(float a, float b) {
    uint32_t r;
    asm("cvt.rn.bf16x2.f32 %0, %1, %2;" : "=r"(r) : "f"(b), "f"(a));
    return r;
}
__device__ __forceinline__ uint32_t pack_f16(float a, float b) {
    uint32_t r;
    asm("cvt.rn.f16x2.f32 %0, %1, %2;" : "=r"(r) : "f"(b), "f"(a));
    return r;
}
__device__ __forceinline__ void split_pack(float x0, float x1, uint32_t& hi, uint32_t& lo) {
    float h0 = bf_hi(x0), h1 = bf_hi(x1);
    hi = pack_bf2(h0, h1);
    lo = pack_bf2(x0 - h0, x1 - h1);
}

#define MMA_TF32(accp, a0, a1, a2, a3, b0, b1)                                  \
    asm volatile(                                                               \
        "mma.sync.aligned.m16n8k8.row.col.f32.tf32.tf32.f32 "                   \
        "{%0,%1,%2,%3}, {%4,%5,%6,%7}, {%8,%9}, {%0,%1,%2,%3};"                 \
        : "+f"((accp)[0]), "+f"((accp)[1]), "+f"((accp)[2]), "+f"((accp)[3])    \
        : "r"(a0), "r"(a1), "r"(a2), "r"(a3), "r"(b0), "r"(b1))

#define MMA_BF16(accp, a0, a1, a2, a3, b0, b1)                                  \
    asm volatile(                                                               \
        "mma.sync.aligned.m16n8k16.row.col.f32.bf16.bf16.f32 "                  \
        "{%0,%1,%2,%3}, {%4,%5,%6,%7}, {%8,%9}, {%0,%1,%2,%3};"                 \
        : "+f"((accp)[0]), "+f"((accp)[1]), "+f"((accp)[2]), "+f"((accp)[3])    \
        : "r"(a0), "r"(a1), "r"(a2), "r"(a3), "r"(b0), "r"(b1))

#define MMA_F16(accp, a0, a1, a2, a3, b0, b1)                                   \
    asm volatile(                                                               \
        "mma.sync.aligned.m16n8k16.row.col.f32.f16.f16.f32 "                    \
        "{%0,%1,%2,%3}, {%4,%5,%6,%7}, {%8,%9}, {%0,%1,%2,%3};"                 \
        : "+f"((accp)[0]), "+f"((accp)[1]), "+f"((accp)[2]), "+f"((accp)[3])    \
        : "r"(a0), "r"(a1), "r"(a2), "r"(a3), "r"(b0), "r"(b1))

// ======== tensor-core GEMM, templated on M-tile and numeric MODE ========
// MODE 0: tf32 (npass 1|3)  MODE 1: bf16x3 (routing-critical)  MODE 2: fp16 1-pass
template<int MT, int MODE>
__global__ void __launch_bounds__(256, MT == 64 ? 2 : 1)
mm_mma_kernel(const float* __restrict__ A, const float* __restrict__ B,
              float* __restrict__ C, const float* __restrict__ bias,
              int Mv, int N, int K,
              long sA, long sB, long sC, long sBias, int ep, int npass)
{
    constexpr int LDA = (MODE == 0) ? 36 : 40;
    constexpr int LDB = (MODE == 0) ? 136 : 132;
    constexpr int MTW  = MT / 32;
    constexpr int AIT  = MT / 32;
    constexpr int ABUF = MT * LDA;
    constexpr int BUFSZ = ABUF + 32 * LDB;
    extern __shared__ float sm[];
    int tid = threadIdx.x, lane = tid & 31, wid = tid >> 5;
    int wm = wid & 1, wn = wid >> 1;
    int r_lo = lane >> 2, c_lo = lane & 3;
    int z = blockIdx.z;
    A += (long)z * sA; B += (long)z * sB; C += (long)z * sC;
    const float* bp = bias ? bias + (long)z * sBias : nullptr;
    int m0 = blockIdx.x * MT, n0 = blockIdx.y * 128;

    float acc[MTW][4][4];
#pragma unroll
    for (int i = 0; i < MTW; i++)
#pragma unroll
        for (int j = 0; j < 4; j++)
#pragma unroll
            for (int k = 0; k < 4; k++) acc[i][j][k] = 0.f;

    float4 pa[AIT], pb[4];

    auto prefetch = [&](int i) {
        int k0 = i << 5;
#pragma unroll
        for (int it = 0; it < AIT; it++) {
            int idx = tid + it * 256;
            int m = idx >> 3, f4 = idx & 7;
            pa[it] = *(const float4*)(A + (size_t)(m0 + m) * K + k0 + f4 * 4);
        }
#pragma unroll
        for (int it = 0; it < 4; it++) {
            int idx = tid + it * 256;
            int k = idx >> 5, f4 = idx & 31;
            pb[it] = *(const float4*)(B + (size_t)(k0 + k) * N + n0 + f4 * 4);
        }
    };
    auto cstore = [&](int s) {
        float* smA = sm + s * BUFSZ;
        float* smB = smA + ABUF;
#pragma unroll
        for (int it = 0; it < AIT; it++) {
            int idx = tid + it * 256;
            int m = idx >> 3, f4 = idx & 7;
            *(float4*)(smA + m * LDA + f4 * 4) = pa[it];
        }
#pragma unroll
        for (int it = 0; it < 4; it++) {
            int idx = tid + it * 256;
            int k = idx >> 5, f4 = idx & 31;
            *(float4*)(smB + k * LDB + f4 * 4) = pb[it];
        }
    };

    int nch = K >> 5;
    prefetch(0);
    cstore(0);
    __syncthreads();
    for (int i = 0; i < nch; i++) {
        if (i + 1 < nch) prefetch(i + 1);
        {
            float* smA = sm + (i & 1) * BUFSZ;
            float* smB = smA + ABUF;
            if constexpr (MODE == 1) {
#pragma unroll
                for (int ks = 0; ks < 2; ks++) {
                    int kb = ks * 16 + 2 * c_lo;
                    uint32_t ah[MTW][4], al[MTW][4], bh[4][2], bl[4][2];
#pragma unroll
                    for (int mt = 0; mt < MTW; mt++) {
                        const float* ab = smA + (wm * (MT / 2) + mt * 16 + r_lo) * LDA + kb;
                        float2 p0 = *(const float2*)ab;
                        float2 p1 = *(const float2*)(ab + 8 * LDA);
                        float2 p2 = *(const float2*)(ab + 8);
                        float2 p3 = *(const float2*)(ab + 8 * LDA + 8);
                        split_pack(p0.x, p0.y, ah[mt][0], al[mt][0]);
                        split_pack(p1.x, p1.y, ah[mt][1], al[mt][1]);
                        split_pack(p2.x, p2.y, ah[mt][2], al[mt][2]);
                        split_pack(p3.x, p3.y, ah[mt][3], al[mt][3]);
                    }
#pragma unroll
                    for (int nt = 0; nt < 4; nt++) {
                        const float* bb = smB + kb * LDB + wn * 32 + nt * 8 + r_lo;
                        split_pack(bb[0],       bb[LDB],     bh[nt][0], bl[nt][0]);
                        split_pack(bb[8 * LDB], bb[9 * LDB], bh[nt][1], bl[nt][1]);
                    }
#pragma unroll
                    for (int mt = 0; mt < MTW; mt++)
#pragma unroll
                        for (int nt = 0; nt < 4; nt++) {
                            MMA_BF16(acc[mt][nt], ah[mt][0], ah[mt][1], ah[mt][2], ah[mt][3],
                                     bh[nt][0], bh[nt][1]);
                            MMA_BF16(acc[mt][nt], ah[mt][0], ah[mt][1], ah[mt][2], ah[mt][3],
                                     bl[nt][0], bl[nt][1]);
                            MMA_BF16(acc[mt][nt], al[mt][0], al[mt][1], al[mt][2], al[mt][3],
                                     bh[nt][0], bh[nt][1]);
                        }
                }
            } else if constexpr (MODE == 2) {
#pragma unroll
                for (int ks = 0; ks < 2; ks++) {
                    int kb = ks * 16 + 2 * c_lo;
                    uint32_t ah[MTW][4], bh[4][2];
#pragma unroll
                    for (int mt = 0; mt < MTW; mt++) {
                        const float* ab = smA + (wm * (MT / 2) + mt * 16 + r_lo) * LDA + kb;
                        float2 p0 = *(const float2*)ab;
                        float2 p1 = *(const float2*)(ab + 8 * LDA);
                        float2 p2 = *(const float2*)(ab + 8);
                        float2 p3 = *(const float2*)(ab + 8 * LDA + 8);
                        ah[mt][0] = pack_f16(p0.x, p0.y);
                        ah[mt][1] = pack_f16(p1.x, p1.y);
                        ah[mt][2] = pack_f16(p2.x, p2.y);
                        ah[mt][3] = pack_f16(p3.x, p3.y);
                    }
#pragma unroll
                    for (int nt = 0; nt < 4; nt++) {
                        const float* bb = smB + kb * LDB + wn * 32 + nt * 8 + r_lo;
                        bh[nt][0] = pack_f16(bb[0], bb[LDB]);
                        bh[nt][1] = pack_f16(bb[8 * LDB], bb[9 * LDB]);
                    }
#pragma unroll
                    for (int mt = 0; mt < MTW; mt++)
#pragma unroll
                        for (int nt = 0; nt < 4; nt++)
                            MMA_F16(acc[mt][nt], ah[mt][0], ah[mt][1], ah[mt][2], ah[mt][3],
                                    bh[nt][0], bh[nt][1]);
                }
            } else {
#pragma unroll
                for (int ks = 0; ks < 4; ks++) {
                    float ar[MTW][4], br[4][2];
                    uint32_t ah[MTW][4], bh[4][2];
#pragma unroll
                    for (int mt = 0; mt < MTW; mt++) {
                        const float* ab = smA + (wm * (MT / 2) + mt * 16 + r_lo) * LDA + ks * 8 + c_lo;
                        ar[mt][0] = ab[0];
                        ar[mt][1] = ab[8 * LDA];
                        ar[mt][2] = ab[4];
                        ar[mt][3] = ab[8 * LDA + 4];
#pragma unroll
                        for (int q = 0; q < 4; q++) ah[mt][q] = __float_as_uint(to_tf32(ar[mt][q]));
                    }
#pragma unroll
                    for (int nt = 0; nt < 4; nt++) {
                        const float* bb = smB + (ks * 8 + c_lo) * LDB + wn * 32 + nt * 8 + r_lo;
                        br[nt][0] = bb[0];
                        br[nt][1] = bb[4 * LDB];
                        bh[nt][0] = __float_as_uint(to_tf32(br[nt][0]));
                        bh[nt][1] = __float_as_uint(to_tf32(br[nt][1]));
                    }
#pragma unroll
                    for (int mt = 0; mt < MTW; mt++)
#pragma unroll
                        for (int nt = 0; nt < 4; nt++)
                            MMA_TF32(acc[mt][nt], ah[mt][0], ah[mt][1], ah[mt][2], ah[mt][3],
                                     bh[nt][0], bh[nt][1]);
                    if (npass == 3) {
#pragma unroll
                        for (int nt = 0; nt < 4; nt++) {
                            br[nt][0] = to_tf32(br[nt][0] - __uint_as_float(bh[nt][0]));
                            br[nt][1] = to_tf32(br[nt][1] - __uint_as_float(bh[nt][1]));
                        }
#pragma unroll
                        for (int mt = 0; mt < MTW; mt++)
#pragma unroll
                            for (int nt = 0; nt < 4; nt++)
                                MMA_TF32(acc[mt][nt], ah[mt][0], ah[mt][1], ah[mt][2], ah[mt][3],
                                         __float_as_uint(br[nt][0]), __float_as_uint(br[nt][1]));
#pragma unroll
                        for (int mt = 0; mt < MTW; mt++)
#pragma unroll
                            for (int q = 0; q < 4; q++)
                                ar[mt][q] = to_tf32(ar[mt][q] - __uint_as_float(ah[mt][q]));
#pragma unroll
                        for (int mt = 0; mt < MTW; mt++)
#pragma unroll
                            for (int nt = 0; nt < 4; nt++)
                                MMA_TF32(acc[mt][nt],
                                         __float_as_uint(ar[mt][0]), __float_as_uint(ar[mt][1]),
                                         __float_as_uint(ar[mt][2]), __float_as_uint(ar[mt][3]),
                                         bh[nt][0], bh[nt][1]);
                    }
                }
            }
        }
        __syncthreads();
        if (i + 1 < nch) {
            cstore((i + 1) & 1);
            __syncthreads();
        }
    }

    int rbase = m0 + wm * (MT / 2) + (lane >> 2);
    int cbase = n0 + wn * 32 + (lane & 3) * 2;
#pragma unroll
    for (int mt = 0; mt < MTW; mt++) {
#pragma unroll
        for (int half = 0; half < 2; half++) {
            int row = rbase + mt * 16 + half * 8;
            if (row >= Mv) continue;
#pragma unroll
            for (int nt = 0; nt < 4; nt++) {
                int col = cbase + nt * 8;
                float x0 = acc[mt][nt][half * 2 + 0];
                float x1 = acc[mt][nt][half * 2 + 1];
                if (ep == 2)      { x0 = gelu_exact(x0 + bp[col]); x1 = gelu_exact(x1 + bp[col + 1]); }
                else if (ep == 3) { x0 += bp[col]; x1 += bp[col + 1]; }
                float* cp = C + (size_t)row * N + col;
                if (ep == 1) { x0 += cp[0]; x1 += cp[1]; }
                float2 o; o.x = x0; o.y = x1;
                *(float2*)cp = o;
            }
        }
    }
}
#define MM_SMEM(MT, LDA, LDB) (2 * ((MT) * (LDA) + 32 * (LDB)) * 4)
#define SM_64_BF  MM_SMEM(64, 40, 132)
#define SM_64_HF  MM_SMEM(64, 40, 132)

// ---------------- embedding gather ----------------
__global__ void embed_kernel(const int* __restrict__ idx, const float* __restrict__ emb,
                             float* __restrict__ x) {
    int i = blockIdx.x * 256 + threadIdx.x;
    int n = i >> 10, c = i & 1023;
    x[i] = emb[(size_t)idx[n] * C_ + c];
}

// ---------------- layernorm ----------------
__global__ void ln_kernel(const float* __restrict__ x, const float* __restrict__ g,
                          const float* __restrict__ b, float* __restrict__ out) {
    int row = blockIdx.x;
    const float* xr = x + (size_t)row * C_;
    float s = 0.f, s2 = 0.f;
    for (int c = threadIdx.x; c < C_; c += 256) { float v = xr[c]; s += v; s2 += v * v; }
    __shared__ float sh1[8], sh2[8], shm[2];
    int lane = threadIdx.x & 31, w = threadIdx.x >> 5;
    s = warp_sum(s); s2 = warp_sum(s2);
    if (!lane) { sh1[w] = s; sh2[w] = s2; }
    __syncthreads();
    if (threadIdx.x == 0) {
        float S = 0.f, S2 = 0.f;
        for (int i = 0; i < 8; i++) { S += sh1[i]; S2 += sh2[i]; }
        float mean = S * (1.0f / C_);
        float var  = S2 * (1.0f / C_) - mean * mean;
        shm[0] = mean; shm[1] = rsqrtf(var + 1e-5f);
    }
    __syncthreads();
    float mean = shm[0], inv = shm[1];
    float* orow = out + (size_t)row * C_;
    for (int c = threadIdx.x; c < C_; c += 256)
        orow[c] = (xr[c] - mean) * inv * g[c] + b[c];
}

// ---------------- RoPE ----------------
__global__ void rope_kernel(float* __restrict__ qkv) {
    int i = blockIdx.x * 256 + threadIdx.x;
    if (i >= NTOK * H_ * (HD_ / 2)) return;
    int j = i & 31;
    int h = (i >> 5) & 15;
    int n = i >> 9;
    int t = n & (T_ - 1);
    float e = (float)(2 * j) / (float)HD_;
    float invf = 1.0f / powf(10000.0f, e);
    float ang = (float)t * invf;
    float s = sinf(ang), c = cosf(ang);
    float* base = qkv + (size_t)n * (3 * C_) + h * (3 * HD_);
    float q1 = base[j],      q2 = base[j + 32];
    base[j]      = q1 * c - q2 * s;
    base[j + 32] = q1 * s + q2 * c;
    float k1 = base[64 + j], k2 = base[64 + j + 32];
    base[64 + j]      = k1 * c - k2 * s;
    base[64 + j + 32] = k1 * s + k2 * c;
}

// ---------------- tensor-core flash attention (bf16x3 QK and PV) ----------------
#define FQ_P 72
#define FV_P 68
#define FP_P 72
#define FA_QS   0
#define FA_KS   (64 * FQ_P)
#define FA_VS   (FA_KS + 64 * FQ_P)
#define FA_PS   (FA_VS + 64 * FV_P)
#define FA_WMAX (FA_PS + 64 * FP_P)
#define FA_WSUM (FA_WMAX + 128)
#define FA_MROW (FA_WSUM + 128)
#define FA_LROW (FA_MROW + 64)
#define FA_AROW (FA_LROW + 64)
#define FA_SMEM ((FA_AROW + 64) * 4)

__global__ void __launch_bounds__(256, 1)
flash_attn_kernel(const float* __restrict__ qkv, float* __restrict__ out) {
    extern __shared__ float fs[];
    float* Qs = fs + FA_QS;
    float* Ks = fs + FA_KS;
    float* Vs = fs + FA_VS;
    float* Ps = fs + FA_PS;
    float* Wmax = fs + FA_WMAX;
    float* Wsum = fs + FA_WSUM;
    float* Mrow = fs + FA_MROW;
    float* Lrow = fs + FA_LROW;
    float* Arow = fs + FA_AROW;
    int bh = blockIdx.y; int b = bh >> 4, h = bh & 15;
    int qb = (int)gridDim.x - 1 - (int)blockIdx.x;
    int q0 = qb * 64;
    int tid = threadIdx.x, lane = tid & 31, wid = tid >> 5;
    int wm = wid & 3, wn = wid >> 2;
    int r_lo = lane >> 2, c_lo = lane & 3;
    int row0 = wm * 16 + r_lo;

    const float* qbase = qkv + (size_t)(b * T_ + q0) * (3 * C_) + h * (3 * HD_);
#pragma unroll
    for (int r = 0; r < 4; r++) {
        int idx = tid + r * 256;
        int tok = idx >> 4, d4 = (idx & 15) * 4;
        *(float4*)(Qs + tok * FQ_P + d4) = *(const float4*)(qbase + (size_t)tok * (3 * C_) + d4);
    }
    if (tid < 64) { Mrow[tid] = -1e30f; Lrow[tid] = 0.f; }

    float oacc[4][4];
#pragma unroll
    for (int nt = 0; nt < 4; nt++)
#pragma unroll
        for (int q = 0; q < 4; q++) oacc[nt][q] = 0.f;

    for (int kb = 0; kb <= qb; kb++) {
        int k0 = kb * 64;
        __syncthreads();
        const float* kbase = qkv + (size_t)(b * T_ + k0) * (3 * C_) + h * (3 * HD_) + HD_;
        const float* vbase = kbase + HD_;
#pragma unroll
        for (int r = 0; r < 4; r++) {
            int idx = tid + r * 256;
            int tok = idx >> 4, d4 = (idx & 15) * 4;
            *(float4*)(Ks + tok * FQ_P + d4) = *(const float4*)(kbase + (size_t)tok * (3 * C_) + d4);
            *(float4*)(Vs + tok * FV_P + d4) = *(const float4*)(vbase + (size_t)tok * (3 * C_) + d4);
        }
        __syncthreads();

        float sacc[4][4];
#pragma unroll
        for (int nt = 0; nt < 4; nt++)
#pragma unroll
            for (int q = 0; q < 4; q++) sacc[nt][q] = 0.f;
#pragma unroll
        for (int sl = 0; sl < 4; sl++) {
            int kb2 = sl * 16 + 2 * c_lo;
            uint32_t ah[4], al[4];
            const float* ab = Qs + (wm * 16 + r_lo) * FQ_P + kb2;
            split_pack(ab[0], ab[1], ah[0], al[0]);
            split_pack(ab[8 * FQ_P], ab[8 * FQ_P + 1], ah[1], al[1]);
            split_pack(ab[8], ab[9], ah[2], al[2]);
            split_pack(ab[8 * FQ_P + 8], ab[8 * FQ_P + 9], ah[3], al[3]);
#pragma unroll
            for (int nt = 0; nt < 4; nt++) {
                const float* bb = Ks + (wn * 32 + nt * 8 + r_lo) * FQ_P + kb2;
                uint32_t bh0, bl0, bh1, bl1;
                split_pack(bb[0], bb[1], bh0, bl0);
                split_pack(bb[8], bb[9], bh1, bl1);
                MMA_BF16(sacc[nt], ah[0], ah[1], ah[2], ah[3], bh0, bh1);
                MMA_BF16(sacc[nt], ah[0], ah[1], ah[2], ah[3], bl0, bl1);
                MMA_BF16(sacc[nt], al[0], al[1], al[2], al[3], bh0, bh1);
            }
        }
        bool diag = (kb == qb);
#pragma unroll
        for (int nt = 0; nt < 4; nt++)
#pragma unroll
            for (int q = 0; q < 4; q++) {
                int rloc = (q >= 2) ? row0 + 8 : row0;
                int cloc = wn * 32 + nt * 8 + 2 * c_lo + (q & 1);
                float v = sacc[nt][q] * 0.125f;
                if (diag && cloc > rloc) v = -1e30f;
                sacc[nt][q] = v;
            }
        float rm0 = -1e30f, rm1 = -1e30f;
#pragma unroll
        for (int nt = 0; nt < 4; nt++) {
            rm0 = fmaxf(rm0, fmaxf(sacc[nt][0], sacc[nt][1]));
            rm1 = fmaxf(rm1, fmaxf(sacc[nt][2], sacc[nt][3]));
        }
        rm0 = fmaxf(rm0, __shfl_xor_sync(0xffffffffu, rm0, 1));
        rm0 = fmaxf(rm0, __shfl_xor_sync(0xffffffffu, rm0, 2));
        rm1 = fmaxf(rm1, __shfl_xor_sync(0xffffffffu, rm1, 1));
        rm1 = fmaxf(rm1, __shfl_xor_sync(0xffffffffu, rm1, 2));
        if (c_lo == 0) {
            Wmax[wn * 64 + row0] = rm0;
            Wmax[wn * 64 + row0 + 8] = rm1;
        }
        __syncthreads();
        float mn0 = fmaxf(Mrow[row0],     fmaxf(Wmax[row0],     Wmax[64 + row0]));
        float mn1 = fmaxf(Mrow[row0 + 8], fmaxf(Wmax[row0 + 8], Wmax[64 + row0 + 8]));
        float rs0 = 0.f, rs1 = 0.f;
#pragma unroll
        for (int nt = 0; nt < 4; nt++) {
            float p0 = expf(sacc[nt][0] - mn0);
            float p1 = expf(sacc[nt][1] - mn0);
            float p2 = expf(sacc[nt][2] - mn1);
            float p3 = expf(sacc[nt][3] - mn1);
            rs0 += p0 + p1; rs1 += p2 + p3;
            int c = wn * 32 + nt * 8 + 2 * c_lo;
            float2 v0; v0.x = p0; v0.y = p1;
            float2 v1; v1.x = p2; v1.y = p3;
            *(float2*)(Ps + (wm * 16 + r_lo) * FP_P + c)       = v0;
            *(float2*)(Ps + (wm * 16 + r_lo + 8) * FP_P + c)   = v1;
        }
        rs0 += __shfl_xor_sync(0xffffffffu, rs0, 1);
        rs0 += __shfl_xor_sync(0xffffffffu, rs0, 2);
        rs1 += __shfl_xor_sync(0xffffffffu, rs1, 1);
        rs1 += __shfl_xor_sync(0xffffffffu, rs1, 2);
        if (c_lo == 0) {
            Wsum[wn * 64 + row0] = rs0;
            Wsum[wn * 64 + row0 + 8] = rs1;
        }
        __syncthreads();
        if (tid < 64) {
            int r = tid;
            float mold = Mrow[r];
            float mn = fmaxf(mold, fmaxf(Wmax[r], Wmax[64 + r]));
            float a = expf(mold - mn);
            Arow[r] = a;
            Lrow[r] = Lrow[r] * a + Wsum[r] + Wsum[64 + r];
            Mrow[r] = mn;
        }
        __syncthreads();
        float a0 = Arow[row0], a1 = Arow[row0 + 8];
#pragma unroll
        for (int nt = 0; nt < 4; nt++) {
            oacc[nt][0] *= a0; oacc[nt][1] *= a0;
            oacc[nt][2] *= a1; oacc[nt][3] *= a1;
        }
#pragma unroll
        for (int sl = 0; sl < 4; sl++) {
            int kb2 = sl * 16 + 2 * c_lo;
            uint32_t ah[4], al[4];
            const float* ab = Ps + (wm * 16 + r_lo) * FP_P + kb2;
            split_pack(ab[0], ab[1], ah[0], al[0]);
            split_pack(ab[8 * FP_P], ab[8 * FP_P + 1], ah[1], al[1]);
            split_pack(ab[8], ab[9], ah[2], al[2]);
            split_pack(ab[8 * FP_P + 8], ab[8 * FP_P + 9], ah[3], al[3]);
#pragma unroll
            for (int nt = 0; nt < 4; nt++) {
                const float* bb = Vs + kb2 * FV_P + wn * 32 + nt * 8 + r_lo;
                uint32_t bh0, bl0, bh1, bl1;
                split_pack(bb[0],          bb[FV_P],     bh0, bl0);
                split_pack(bb[8 * FV_P],   bb[9 * FV_P], bh1, bl1);
                MMA_BF16(oacc[nt], ah[0], ah[1], ah[2], ah[3], bh0, bh1);
                MMA_BF16(oacc[nt], ah[0], ah[1], ah[2], ah[3], bl0, bl1);
                MMA_BF16(oacc[nt], al[0], al[1], al[2], al[3], bh0, bh1);
            }
        }
    }

    float l0 = 1.0f / Lrow[row0], l1 = 1.0f / Lrow[row0 + 8];
#pragma unroll
    for (int nt = 0; nt < 4; nt++) {
        int col = wn * 32 + nt * 8 + 2 * c_lo;
        float2 v0; v0.x = oacc[nt][0] * l0; v0.y = oacc[nt][1] * l0;
        float2 v1; v1.x = oacc[nt][2] * l1; v1.y = oacc[nt][3] * l1;
        *(float2*)(out + (size_t)(b * T_ + q0 + row0) * C_ + h * HD_ + col)     = v0;
        *(float2*)(out + (size_t)(b * T_ + q0 + row0 + 8) * C_ + h * HD_ + col) = v1;
    }
}

// ---------------- gating ----------------
__global__ void gate_kernel(const float* __restrict__ x, const float* __restrict__ gw,
                            float* __restrict__ gates, int* __restrict__ top) {
    int n = blockIdx.x;
    int lane = threadIdx.x & 31, w = threadIdx.x >> 5;
    const float* xr = x + (size_t)n * C_;
    float acc = 0.f;
    for (int c = lane; c < C_; c += 32) acc += xr[c] * gw[(size_t)c * E_ + w];
    acc = warp_sum(acc);
    __shared__ float sl[E_];
    if (!lane) sl[w] = acc;
    __syncthreads();
    if (threadIdx.x == 0) {
        float p[E_];
        float m = sl[0];
        for (int e = 1; e < E_; e++) m = fmaxf(m, sl[e]);
        float s = 0.f;
        for (int e = 0; e < E_; e++) { p[e] = expf(sl[e] - m); s += p[e]; }
        float inv = 1.0f / s;
        for (int e = 0; e < E_; e++) { p[e] *= inv; gates[(size_t)n * E_ + e] = p[e]; }
        int i0 = 0;
        for (int e = 1; e < E_; e++) if (p[e] > p[i0]) i0 = e;
        int i1 = -1;
        for (int e = 0; e < E_; e++) {
            if (e == i0) continue;
            if (i1 < 0 || p[e] > p[i1]) i1 = e;
        }
        top[2 * n] = i0; top[2 * n + 1] = i1;
    }
}

// ---------------- routing: warp-parallel per-expert prefix (exact token order) ----
__global__ void route_kernel(const int* __restrict__ top, int* __restrict__ slot) {
    int e = threadIdx.x >> 5, lane = threadIdx.x & 31;
    int cnt = 0;
    for (int base = 0; base < NTOK; base += 32) {
        int n = base + lane;
        int t0 = top[2 * n], t1 = top[2 * n + 1];
        bool m = (t0 == e) || (t1 == e);
        unsigned ball = __ballot_sync(0xffffffffu, m);
        if (m) {
            int pos = cnt + __popc(ball & ((1u << lane) - 1));
            int s = (pos < CAP) ? pos : -1;
            if (t0 == e) slot[2 * n] = s; else slot[2 * n + 1] = s;
        }
        cnt += __popc(ball);
    }
}

// ---------------- scatter ----------------
__global__ void scatter_kernel(const float* __restrict__ ln, const int* __restrict__ top,
                               const int* __restrict__ slot, float* __restrict__ buf) {
    int n = blockIdx.x;
    const float4* src = (const float4*)(ln + (size_t)n * C_);
#pragma unroll
    for (int kk = 0; kk < 2; kk++) {
        int s = slot[2 * n + kk];
        if (s < 0) continue;
        int e = top[2 * n + kk];
        float4* dst = (float4*)(buf + ((size_t)e * CAP + s) * C_);
        for (int i = threadIdx.x; i < C_ / 4; i += 256) dst[i] = src[i];
    }
}

// ---------------- combine + residual ----------------
__global__ void combine_kernel(const float* __restrict__ y, const float* __restrict__ gates,
                               const int* __restrict__ top, const int* __restrict__ slot,
                               float* __restrict__ x) {
    int n = blockIdx.x;
    int e0 = top[2 * n], e1 = top[2 * n + 1];
    int s0 = slot[2 * n], s1 = slot[2 * n + 1];
    float w0 = (s0 >= 0) ? gates[(size_t)n * E_ + e0] : 0.f;
    float w1 = (s1 >= 0) ? gates[(size_t)n * E_ + e1] : 0.f;
    const float* y0 = y + ((size_t)e0 * CAP + (s0 >= 0 ? s0 : 0)) * C_;
    const float* y1 = y + ((size_t)e1 * CAP + (s1 >= 0 ? s1 : 0)) * C_;
    float* xr = x + (size_t)n * C_;
    for (int c = threadIdx.x; c < C_; c += 256)
        xr[c] += w0 * y0[c] + w1 * y1[c];
}

// ---------------- launch ----------------
extern "C" void kernel_launch(void* const* d_in, const int* in_sizes, int n_in,
                              void* d_out, int out_size) {
    const int*   idx     = (const int*)  d_in[0];
    const float* tok_emb = (const float*)d_in[1];
    const float* ln1_g   = (const float*)d_in[2];
    const float* ln1_b   = (const float*)d_in[3];
    const float* qkv_w   = (const float*)d_in[4];
    const float* proj_w  = (const float*)d_in[5];
    const float* ln2_g   = (const float*)d_in[6];
    const float* ln2_b   = (const float*)d_in[7];
    const float* gate_w  = (const float*)d_in[8];
    const float* w1      = (const float*)d_in[9];
    const float* b1      = (const float*)d_in[10];
    const float* w2      = (const float*)d_in[11];
    const float* b2      = (const float*)d_in[12];
    const float* lnf_g   = (const float*)d_in[13];
    const float* lnf_b   = (const float*)d_in[14];
    const float* lm_head = (const float*)d_in[15];
    float* out = (float*)d_out;

    float *x, *ln, *qkv, *attn, *gates, *buf, *hbuf, *ybuf;
    int *top, *slot;
    cudaGetSymbolAddress((void**)&x,     g_x);
    cudaGetSymbolAddress((void**)&ln,    g_ln);
    cudaGetSymbolAddress((void**)&qkv,   g_qkv);
    cudaGetSymbolAddress((void**)&attn,  g_attn);
    cudaGetSymbolAddress((void**)&gates, g_gates);
    cudaGetSymbolAddress((void**)&top,   g_top);
    cudaGetSymbolAddress((void**)&slot,  g_slot);
    cudaGetSymbolAddress((void**)&buf,   g_buf);
    cudaGetSymbolAddress((void**)&hbuf,  g_hbuf);
    cudaGetSymbolAddress((void**)&ybuf,  g_ybuf);

    cudaFuncSetAttribute((const void*)mm_mma_kernel<64, 1>, cudaFuncAttributeMaxDynamicSharedMemorySize, SM_64_BF);
    cudaFuncSetAttribute((const void*)mm_mma_kernel<64, 2>, cudaFuncAttributeMaxDynamicSharedMemorySize, SM_64_HF);
    cudaFuncSetAttribute((const void*)flash_attn_kernel, cudaFuncAttributeMaxDynamicSharedMemorySize, FA_SMEM);

    embed_kernel<<<NTOK * C_ / 256, 256>>>(idx, tok_emb, x);

    for (int l = 0; l < L_; l++) {
        // --- attention (routing-critical -> bf16x3; MT=64, occupancy 2) ---
        ln_kernel<<<NTOK, 256>>>(x, ln1_g + (size_t)l * C_, ln1_b + (size_t)l * C_, ln);
        mm_mma_kernel<64, 1><<<dim3(NTOK / 64, 3 * C_ / 128, 1), 256, SM_64_BF>>>(
            ln, qkv_w + (size_t)l * C_ * 3 * C_, qkv, nullptr,
            NTOK, 3 * C_, C_, 0, 0, 0, 0, 0, 3);
        rope_kernel<<<(NTOK * H_ * (HD_ / 2) + 255) / 256, 256>>>(qkv);
        flash_attn_kernel<<<dim3(T_ / 64, B_ * H_), 256, FA_SMEM>>>(qkv, attn);
        mm_mma_kernel<64, 1><<<dim3(NTOK / 64, C_ / 128, 1), 256, SM_64_BF>>>(
            attn, proj_w + (size_t)l * C_ * C_, x, nullptr,
            NTOK, C_, C_, 0, 0, 0, 0, 1, 3);  // += residual

        // --- MoE ---
        ln_kernel<<<NTOK, 256>>>(x, ln2_g + (size_t)l * C_, ln2_b + (size_t)l * C_, ln);
        gate_kernel<<<NTOK, 256>>>(ln, gate_w + (size_t)l * C_ * E_, gates, top);
        route_kernel<<<1, 256>>>(top, slot);
        scatter_kernel<<<NTOK, 256>>>(ln, top, slot, buf);
        if (l < L_ - 1) {
            mm_mma_kernel<64, 1><<<dim3(CAP / 64, FF_ / 128, E_), 256, SM_64_BF>>>(
                buf, w1 + (size_t)l * E_ * C_ * FF_, hbuf, b1 + (size_t)l * E_ * FF_,
                CAP, FF_, C_, (long)CAP * C_, (long)C_ * FF_, (long)CAP * FF_, (long)FF_, 2, 3);
            mm_mma_kernel<64, 1><<<dim3(CAP / 64, C_ / 128, E_), 256, SM_64_BF>>>(
                hbuf, w2 + (size_t)l * E_ * FF_ * C_, ybuf, b2 + (size_t)l * E_ * C_,
                CAP, C_, FF_, (long)CAP * FF_, (long)FF_ * C_, (long)CAP * C_, (long)C_, 3, 3);
        } else {
            mm_mma_kernel<64, 2><<<dim3(CAP / 64, FF_ / 128, E_), 256, SM_64_HF>>>(
                buf, w1 + (size_t)l * E_ * C_ * FF_, hbuf, b1 + (size_t)l * E_ * FF_,
                CAP, FF_, C_, (long)CAP * C_, (long)C_ * FF_, (long)CAP * FF_, (long)FF_, 2, 1);
            mm_mma_kernel<64, 2><<<dim3(CAP / 64, C_ / 128, E_), 256, SM_64_HF>>>(
                hbuf, w2 + (size_t)l * E_ * FF_ * C_, ybuf, b2 + (size_t)l * E_ * C_,
                CAP, C_, FF_, (long)CAP * FF_, (long)FF_ * C_, (long)CAP * C_, (long)C_, 3, 1);
        }
        combine_kernel<<<NTOK, 256>>>(ybuf, gates, top, slot, x);
    }

    ln_kernel<<<NTOK, 256>>>(x, lnf_g, lnf_b, ln);
    mm_mma_kernel<64, 2><<<dim3(NTOK / 64, V_ / 128, 1), 256, SM_64_HF>>>(
        ln, lm_head, out, nullptr, NTOK, V_, C_, 0, 0, 0, 0, 0, 1);
}

// round 14
// speedup vs baseline: 1.0848x; 1.0848x over previous
#include <cuda_runtime.h>
#include <cuda_bf16.h>
#include <cuda_fp16.h>
#include <math.h>
#include <stdint.h>

#define B_   2
#define T_   1024
#define C_   1024
#define H_   16
#define HD_  64
#define L_   2
#define E_   8
#define FF_  4096
#define V_   32000
#define NTOK (B_ * T_)
#define CAP  320   // ceil(1.25 * 2048 / 8); 320 = 5 * 64 -> exact 64-row tiling

// ---------------- scratch (static device globals; no allocations) ----------------
__device__ float g_x[NTOK * C_];
__device__ float g_ln[NTOK * C_];
__device__ float g_qkv[NTOK * 3 * C_];
__device__ float g_attn[NTOK * C_];
__device__ float g_gates[NTOK * E_];
__device__ int   g_top[NTOK * 2];
__device__ int   g_slot[NTOK * 2];
__device__ int   g_inv[E_ * CAP];
__device__ float g_hbuf[E_ * CAP * FF_];
__device__ float g_ybuf[E_ * CAP * C_];

// ---------------- helpers ----------------
__device__ __forceinline__ float warp_sum(float v) {
#pragma unroll
    for (int o = 16; o; o >>= 1) v += __shfl_xor_sync(0xffffffffu, v, o);
    return v;
}
__device__ __forceinline__ float gelu_exact(float v) {
    return 0.5f * v * (1.0f + erff(v * 0.70710678118654752f));
}
__device__ __forceinline__ float to_tf32(float v) {
    float o; asm("cvt.rna.tf32.f32 %0, %1;" : "=f"(o) : "f"(v)); return o;
}
__device__ __forceinline__ float bf_hi(float v) {
    return __bfloat162float(__float2bfloat16(v));
}
__device__ __forceinline__ uint32_t pack_bf2(float a, float b) {
    uint32_t r;
    asm("cvt.rn.bf16x2.f32 %0, %1, %2;" : "=r"(r) : "f"(b), "f"(a));
    return r;
}
__device__ __forceinline__ uint32_t pack_f16(float a, float b) {
    uint32_t r;
    asm("cvt.rn.f16x2.f32 %0, %1, %2;" : "=r"(r) : "f"(b), "f"(a));
    return r;
}
__device__ __forceinline__ void split_pack(float x0, float x1, uint32_t& hi, uint32_t& lo) {
    float h0 = bf_hi(x0), h1 = bf_hi(x1);
    hi = pack_bf2(h0, h1);
    lo = pack_bf2(x0 - h0, x1 - h1);
}

#define MMA_TF32(accp, a0, a1, a2, a3, b0, b1)                                  \
    asm volatile(                                                               \
        "mma.sync.aligned.m16n8k8.row.col.f32.tf32.tf32.f32 "                   \
        "{%0,%1,%2,%3}, {%4,%5,%6,%7}, {%8,%9}, {%0,%1,%2,%3};"                 \
        : "+f"((accp)[0]), "+f"((accp)[1]), "+f"((accp)[2]), "+f"((accp)[3])    \
        : "r"(a0), "r"(a1), "r"(a2), "r"(a3), "r"(b0), "r"(b1))

#define MMA_BF16(accp, a0, a1, a2, a3, b0, b1)                                  \
    asm volatile(                                                               \
        "mma.sync.aligned.m16n8k16.row.col.f32.bf16.bf16.f32 "                  \
        "{%0,%1,%2,%3}, {%4,%5,%6,%7}, {%8,%9}, {%0,%1,%2,%3};"                 \
        : "+f"((accp)[0]), "+f"((accp)[1]), "+f"((accp)[2]), "+f"((accp)[3])    \
        : "r"(a0), "r"(a1), "r"(a2), "r"(a3), "r"(b0), "r"(b1))

#define MMA_F16(accp, a0, a1, a2, a3, b0, b1)                                   \
    asm volatile(                                                               \
        "mma.sync.aligned.m16n8k16.row.col.f32.f16.f16.f32 "                    \
        "{%0,%1,%2,%3}, {%4,%5,%6,%7}, {%8,%9}, {%0,%1,%2,%3};"                 \
        : "+f"((accp)[0]), "+f"((accp)[1]), "+f"((accp)[2]), "+f"((accp)[3])    \
        : "r"(a0), "r"(a1), "r"(a2), "r"(a3), "r"(b0), "r"(b1))

// ======== tensor-core GEMM, templated on M-tile, numeric MODE, A-row gather ========
// MODE 0: tf32 (npass 1|3)  MODE 1: bf16x3 (routing-critical)  MODE 2: fp16 1-pass
// GATHER: A row m is read from A[gidx[z*CAP + m0 + m] * K + ...] (MoE dispatch).
template<int MT, int MODE, bool GATHER>
__global__ void __launch_bounds__(256, MT == 64 ? 2 : 1)
mm_mma_kernel(const float* __restrict__ A, const float* __restrict__ B,
              float* __restrict__ C, const float* __restrict__ bias,
              const int* __restrict__ gidx,
              int Mv, int N, int K,
              long sA, long sB, long sC, long sBias, int ep, int npass)
{
    constexpr int LDA = (MODE == 0) ? 36 : 40;
    constexpr int LDB = (MODE == 0) ? 136 : 132;
    constexpr int MTW  = MT / 32;
    constexpr int AIT  = MT / 32;
    constexpr int ABUF = MT * LDA;
    constexpr int BUFSZ = ABUF + 32 * LDB;
    extern __shared__ float sm[];
    int tid = threadIdx.x, lane = tid & 31, wid = tid >> 5;
    int wm = wid & 1, wn = wid >> 1;
    int r_lo = lane >> 2, c_lo = lane & 3;
    int z = blockIdx.z;
    A += (long)z * sA; B += (long)z * sB; C += (long)z * sC;
    const float* bp = bias ? bias + (long)z * sBias : nullptr;
    int m0 = blockIdx.x * MT, n0 = blockIdx.y * 128;

    // per-thread A-row gather indices (2 rows per thread per AIT iter)
    int grow[AIT];
    if (GATHER) {
#pragma unroll
        for (int it = 0; it < AIT; it++) {
            int idx = tid + it * 256;
            grow[it] = gidx[z * CAP + m0 + (idx >> 3)];
        }
    }

    float acc[MTW][4][4];
#pragma unroll
    for (int i = 0; i < MTW; i++)
#pragma unroll
        for (int j = 0; j < 4; j++)
#pragma unroll
            for (int k = 0; k < 4; k++) acc[i][j][k] = 0.f;

    float4 pa[AIT], pb[4];

    auto prefetch = [&](int i) {
        int k0 = i << 5;
#pragma unroll
        for (int it = 0; it < AIT; it++) {
            int idx = tid + it * 256;
            int m = idx >> 3, f4 = idx & 7;
            long arow = GATHER ? (long)grow[it] : (long)(m0 + m);
            pa[it] = *(const float4*)(A + (size_t)arow * K + k0 + f4 * 4);
        }
#pragma unroll
        for (int it = 0; it < 4; it++) {
            int idx = tid + it * 256;
            int k = idx >> 5, f4 = idx & 31;
            pb[it] = *(const float4*)(B + (size_t)(k0 + k) * N + n0 + f4 * 4);
        }
    };
    auto cstore = [&](int s) {
        float* smA = sm + s * BUFSZ;
        float* smB = smA + ABUF;
#pragma unroll
        for (int it = 0; it < AIT; it++) {
            int idx = tid + it * 256;
            int m = idx >> 3, f4 = idx & 7;
            *(float4*)(smA + m * LDA + f4 * 4) = pa[it];
        }
#pragma unroll
        for (int it = 0; it < 4; it++) {
            int idx = tid + it * 256;
            int k = idx >> 5, f4 = idx & 31;
            *(float4*)(smB + k * LDB + f4 * 4) = pb[it];
        }
    };

    int nch = K >> 5;
    prefetch(0);
    cstore(0);
    __syncthreads();
    for (int i = 0; i < nch; i++) {
        if (i + 1 < nch) prefetch(i + 1);
        {
            float* smA = sm + (i & 1) * BUFSZ;
            float* smB = smA + ABUF;
            if constexpr (MODE == 1) {
#pragma unroll
                for (int ks = 0; ks < 2; ks++) {
                    int kb = ks * 16 + 2 * c_lo;
                    uint32_t ah[MTW][4], al[MTW][4], bh[4][2], bl[4][2];
#pragma unroll
                    for (int mt = 0; mt < MTW; mt++) {
                        const float* ab = smA + (wm * (MT / 2) + mt * 16 + r_lo) * LDA + kb;
                        float2 p0 = *(const float2*)ab;
                        float2 p1 = *(const float2*)(ab + 8 * LDA);
                        float2 p2 = *(const float2*)(ab + 8);
                        float2 p3 = *(const float2*)(ab + 8 * LDA + 8);
                        split_pack(p0.x, p0.y, ah[mt][0], al[mt][0]);
                        split_pack(p1.x, p1.y, ah[mt][1], al[mt][1]);
                        split_pack(p2.x, p2.y, ah[mt][2], al[mt][2]);
                        split_pack(p3.x, p3.y, ah[mt][3], al[mt][3]);
                    }
#pragma unroll
                    for (int nt = 0; nt < 4; nt++) {
                        const float* bb = smB + kb * LDB + wn * 32 + nt * 8 + r_lo;
                        split_pack(bb[0],       bb[LDB],     bh[nt][0], bl[nt][0]);
                        split_pack(bb[8 * LDB], bb[9 * LDB], bh[nt][1], bl[nt][1]);
                    }
#pragma unroll
                    for (int mt = 0; mt < MTW; mt++)
#pragma unroll
                        for (int nt = 0; nt < 4; nt++) {
                            MMA_BF16(acc[mt][nt], ah[mt][0], ah[mt][1], ah[mt][2], ah[mt][3],
                                     bh[nt][0], bh[nt][1]);
                            MMA_BF16(acc[mt][nt], ah[mt][0], ah[mt][1], ah[mt][2], ah[mt][3],
                                     bl[nt][0], bl[nt][1]);
                            MMA_BF16(acc[mt][nt], al[mt][0], al[mt][1], al[mt][2], al[mt][3],
                                     bh[nt][0], bh[nt][1]);
                        }
                }
            } else if constexpr (MODE == 2) {
#pragma unroll
                for (int ks = 0; ks < 2; ks++) {
                    int kb = ks * 16 + 2 * c_lo;
                    uint32_t ah[MTW][4], bh[4][2];
#pragma unroll
                    for (int mt = 0; mt < MTW; mt++) {
                        const float* ab = smA + (wm * (MT / 2) + mt * 16 + r_lo) * LDA + kb;
                        float2 p0 = *(const float2*)ab;
                        float2 p1 = *(const float2*)(ab + 8 * LDA);
                        float2 p2 = *(const float2*)(ab + 8);
                        float2 p3 = *(const float2*)(ab + 8 * LDA + 8);
                        ah[mt][0] = pack_f16(p0.x, p0.y);
                        ah[mt][1] = pack_f16(p1.x, p1.y);
                        ah[mt][2] = pack_f16(p2.x, p2.y);
                        ah[mt][3] = pack_f16(p3.x, p3.y);
                    }
#pragma unroll
                    for (int nt = 0; nt < 4; nt++) {
                        const float* bb = smB + kb * LDB + wn * 32 + nt * 8 + r_lo;
                        bh[nt][0] = pack_f16(bb[0], bb[LDB]);
                        bh[nt][1] = pack_f16(bb[8 * LDB], bb[9 * LDB]);
                    }
#pragma unroll
                    for (int mt = 0; mt < MTW; mt++)
#pragma unroll
                        for (int nt = 0; nt < 4; nt++)
                            MMA_F16(acc[mt][nt], ah[mt][0], ah[mt][1], ah[mt][2], ah[mt][3],
                                    bh[nt][0], bh[nt][1]);
                }
            } else {
#pragma unroll
                for (int ks = 0; ks < 4; ks++) {
                    float ar[MTW][4], br[4][2];
                    uint32_t ah[MTW][4], bh[4][2];
#pragma unroll
                    for (int mt = 0; mt < MTW; mt++) {
                        const float* ab = smA + (wm * (MT / 2) + mt * 16 + r_lo) * LDA + ks * 8 + c_lo;
                        ar[mt][0] = ab[0];
                        ar[mt][1] = ab[8 * LDA];
                        ar[mt][2] = ab[4];
                        ar[mt][3] = ab[8 * LDA + 4];
#pragma unroll
                        for (int q = 0; q < 4; q++) ah[mt][q] = __float_as_uint(to_tf32(ar[mt][q]));
                    }
#pragma unroll
                    for (int nt = 0; nt < 4; nt++) {
                        const float* bb = smB + (ks * 8 + c_lo) * LDB + wn * 32 + nt * 8 + r_lo;
                        br[nt][0] = bb[0];
                        br[nt][1] = bb[4 * LDB];
                        bh[nt][0] = __float_as_uint(to_tf32(br[nt][0]));
                        bh[nt][1] = __float_as_uint(to_tf32(br[nt][1]));
                    }
#pragma unroll
                    for (int mt = 0; mt < MTW; mt++)
#pragma unroll
                        for (int nt = 0; nt < 4; nt++)
                            MMA_TF32(acc[mt][nt], ah[mt][0], ah[mt][1], ah[mt][2], ah[mt][3],
                                     bh[nt][0], bh[nt][1]);
                    if (npass == 3) {
#pragma unroll
                        for (int nt = 0; nt < 4; nt++) {
                            br[nt][0] = to_tf32(br[nt][0] - __uint_as_float(bh[nt][0]));
                            br[nt][1] = to_tf32(br[nt][1] - __uint_as_float(bh[nt][1]));
                        }
#pragma unroll
                        for (int mt = 0; mt < MTW; mt++)
#pragma unroll
                            for (int nt = 0; nt < 4; nt++)
                                MMA_TF32(acc[mt][nt], ah[mt][0], ah[mt][1], ah[mt][2], ah[mt][3],
                                         __float_as_uint(br[nt][0]), __float_as_uint(br[nt][1]));
#pragma unroll
                        for (int mt = 0; mt < MTW; mt++)
#pragma unroll
                            for (int q = 0; q < 4; q++)
                                ar[mt][q] = to_tf32(ar[mt][q] - __uint_as_float(ah[mt][q]));
#pragma unroll
                        for (int mt = 0; mt < MTW; mt++)
#pragma unroll
                            for (int nt = 0; nt < 4; nt++)
                                MMA_TF32(acc[mt][nt],
                                         __float_as_uint(ar[mt][0]), __float_as_uint(ar[mt][1]),
                                         __float_as_uint(ar[mt][2]), __float_as_uint(ar[mt][3]),
                                         bh[nt][0], bh[nt][1]);
                    }
                }
            }
        }
        __syncthreads();
        if (i + 1 < nch) {
            cstore((i + 1) & 1);
            __syncthreads();
        }
    }

    int rbase = m0 + wm * (MT / 2) + (lane >> 2);
    int cbase = n0 + wn * 32 + (lane & 3) * 2;
#pragma unroll
    for (int mt = 0; mt < MTW; mt++) {
#pragma unroll
        for (int half = 0; half < 2; half++) {
            int row = rbase + mt * 16 + half * 8;
            if (row >= Mv) continue;
#pragma unroll
            for (int nt = 0; nt < 4; nt++) {
                int col = cbase + nt * 8;
                float x0 = acc[mt][nt][half * 2 + 0];
                float x1 = acc[mt][nt][half * 2 + 1];
                if (ep == 2)      { x0 = gelu_exact(x0 + bp[col]); x1 = gelu_exact(x1 + bp[col + 1]); }
                else if (ep == 3) { x0 += bp[col]; x1 += bp[col + 1]; }
                float* cp = C + (size_t)row * N + col;
                if (ep == 1) { x0 += cp[0]; x1 += cp[1]; }
                float2 o; o.x = x0; o.y = x1;
                *(float2*)cp = o;
            }
        }
    }
}
#define MM_SMEM(MT, LDA, LDB) (2 * ((MT) * (LDA) + 32 * (LDB)) * 4)
#define SM_128   MM_SMEM(128, 40, 132)
#define SM_64    MM_SMEM(64, 40, 132)

// ---------------- embedding gather ----------------
__global__ void embed_kernel(const int* __restrict__ idx, const float* __restrict__ emb,
                             float* __restrict__ x) {
    int i = blockIdx.x * 256 + threadIdx.x;
    int n = i >> 10, c = i & 1023;
    x[i] = emb[(size_t)idx[n] * C_ + c];
}

// ---------------- layernorm ----------------
__global__ void ln_kernel(const float* __restrict__ x, const float* __restrict__ g,
                          const float* __restrict__ b, float* __restrict__ out) {
    int row = blockIdx.x;
    const float* xr = x + (size_t)row * C_;
    float s = 0.f, s2 = 0.f;
    for (int c = threadIdx.x; c < C_; c += 256) { float v = xr[c]; s += v; s2 += v * v; }
    __shared__ float sh1[8], sh2[8], shm[2];
    int lane = threadIdx.x & 31, w = threadIdx.x >> 5;
    s = warp_sum(s); s2 = warp_sum(s2);
    if (!lane) { sh1[w] = s; sh2[w] = s2; }
    __syncthreads();
    if (threadIdx.x == 0) {
        float S = 0.f, S2 = 0.f;
        for (int i = 0; i < 8; i++) { S += sh1[i]; S2 += sh2[i]; }
        float mean = S * (1.0f / C_);
        float var  = S2 * (1.0f / C_) - mean * mean;
        shm[0] = mean; shm[1] = rsqrtf(var + 1e-5f);
    }
    __syncthreads();
    float mean = shm[0], inv = shm[1];
    float* orow = out + (size_t)row * C_;
    for (int c = threadIdx.x; c < C_; c += 256)
        orow[c] = (xr[c] - mean) * inv * g[c] + b[c];
}

// ---------------- fused layernorm + gate (MoE path) ----------------
// Writes LN row (for w1 gather) AND computes gates/top2 from smem copy.
__global__ void lngate_kernel(const float* __restrict__ x, const float* __restrict__ g,
                              const float* __restrict__ b, const float* __restrict__ gw,
                              float* __restrict__ out, float* __restrict__ gates,
                              int* __restrict__ top) {
    int row = blockIdx.x;
    const float* xr = x + (size_t)row * C_;
    __shared__ float sh1[8], sh2[8], shm[2], lnrow[C_], sl[E_];
    int lane = threadIdx.x & 31, w = threadIdx.x >> 5;
    float s = 0.f, s2 = 0.f;
    for (int c = threadIdx.x; c < C_; c += 256) { float v = xr[c]; s += v; s2 += v * v; }
    s = warp_sum(s); s2 = warp_sum(s2);
    if (!lane) { sh1[w] = s; sh2[w] = s2; }
    __syncthreads();
    if (threadIdx.x == 0) {
        float S = 0.f, S2 = 0.f;
        for (int i = 0; i < 8; i++) { S += sh1[i]; S2 += sh2[i]; }
        float mean = S * (1.0f / C_);
        float var  = S2 * (1.0f / C_) - mean * mean;
        shm[0] = mean; shm[1] = rsqrtf(var + 1e-5f);
    }
    __syncthreads();
    float mean = shm[0], inv = shm[1];
    float* orow = out + (size_t)row * C_;
    for (int c = threadIdx.x; c < C_; c += 256) {
        float v = (xr[c] - mean) * inv * g[c] + b[c];
        lnrow[c] = v;
        orow[c] = v;
    }
    __syncthreads();
    // gate: warp w computes expert w's logit from the smem LN row
    float acc = 0.f;
    for (int c = lane; c < C_; c += 32) acc += lnrow[c] * gw[(size_t)c * E_ + w];
    acc = warp_sum(acc);
    if (!lane) sl[w] = acc;
    __syncthreads();
    if (threadIdx.x == 0) {
        float p[E_];
        float m = sl[0];
        for (int e = 1; e < E_; e++) m = fmaxf(m, sl[e]);
        float ssum = 0.f;
        for (int e = 0; e < E_; e++) { p[e] = expf(sl[e] - m); ssum += p[e]; }
        float invs = 1.0f / ssum;
        for (int e = 0; e < E_; e++) { p[e] *= invs; gates[(size_t)row * E_ + e] = p[e]; }
        int i0 = 0;
        for (int e = 1; e < E_; e++) if (p[e] > p[i0]) i0 = e;
        int i1 = -1;
        for (int e = 0; e < E_; e++) {
            if (e == i0) continue;
            if (i1 < 0 || p[e] > p[i1]) i1 = e;
        }
        top[2 * row] = i0; top[2 * row + 1] = i1;
    }
}

// ---------------- RoPE ----------------
__global__ void rope_kernel(float* __restrict__ qkv) {
    int i = blockIdx.x * 256 + threadIdx.x;
    if (i >= NTOK * H_ * (HD_ / 2)) return;
    int j = i & 31;
    int h = (i >> 5) & 15;
    int n = i >> 9;
    int t = n & (T_ - 1);
    float e = (float)(2 * j) / (float)HD_;
    float invf = 1.0f / powf(10000.0f, e);
    float ang = (float)t * invf;
    float s = sinf(ang), c = cosf(ang);
    float* base = qkv + (size_t)n * (3 * C_) + h * (3 * HD_);
    float q1 = base[j],      q2 = base[j + 32];
    base[j]      = q1 * c - q2 * s;
    base[j + 32] = q1 * s + q2 * c;
    float k1 = base[64 + j], k2 = base[64 + j + 32];
    base[64 + j]      = k1 * c - k2 * s;
    base[64 + j + 32] = k1 * s + k2 * c;
}

// ---------------- tensor-core flash attention (bf16x3 QK and PV) ----------------
#define FQ_P 72
#define FV_P 68
#define FP_P 72
#define FA_QS   0
#define FA_KS   (64 * FQ_P)
#define FA_VS   (FA_KS + 64 * FQ_P)
#define FA_PS   (FA_VS + 64 * FV_P)
#define FA_WMAX (FA_PS + 64 * FP_P)
#define FA_WSUM (FA_WMAX + 128)
#define FA_MROW (FA_WSUM + 128)
#define FA_LROW (FA_MROW + 64)
#define FA_AROW (FA_LROW + 64)
#define FA_SMEM ((FA_AROW + 64) * 4)

__global__ void __launch_bounds__(256, 1)
flash_attn_kernel(const float* __restrict__ qkv, float* __restrict__ out) {
    extern __shared__ float fs[];
    float* Qs = fs + FA_QS;
    float* Ks = fs + FA_KS;
    float* Vs = fs + FA_VS;
    float* Ps = fs + FA_PS;
    float* Wmax = fs + FA_WMAX;
    float* Wsum = fs + FA_WSUM;
    float* Mrow = fs + FA_MROW;
    float* Lrow = fs + FA_LROW;
    float* Arow = fs + FA_AROW;
    int bh = blockIdx.y; int b = bh >> 4, h = bh & 15;
    int qb = (int)gridDim.x - 1 - (int)blockIdx.x;
    int q0 = qb * 64;
    int tid = threadIdx.x, lane = tid & 31, wid = tid >> 5;
    int wm = wid & 3, wn = wid >> 2;
    int r_lo = lane >> 2, c_lo = lane & 3;
    int row0 = wm * 16 + r_lo;

    const float* qbase = qkv + (size_t)(b * T_ + q0) * (3 * C_) + h * (3 * HD_);
#pragma unroll
    for (int r = 0; r < 4; r++) {
        int idx = tid + r * 256;
        int tok = idx >> 4, d4 = (idx & 15) * 4;
        *(float4*)(Qs + tok * FQ_P + d4) = *(const float4*)(qbase + (size_t)tok * (3 * C_) + d4);
    }
    if (tid < 64) { Mrow[tid] = -1e30f; Lrow[tid] = 0.f; }

    float oacc[4][4];
#pragma unroll
    for (int nt = 0; nt < 4; nt++)
#pragma unroll
        for (int q = 0; q < 4; q++) oacc[nt][q] = 0.f;

    for (int kb = 0; kb <= qb; kb++) {
        int k0 = kb * 64;
        __syncthreads();
        const float* kbase = qkv + (size_t)(b * T_ + k0) * (3 * C_) + h * (3 * HD_) + HD_;
        const float* vbase = kbase + HD_;
#pragma unroll
        for (int r = 0; r < 4; r++) {
            int idx = tid + r * 256;
            int tok = idx >> 4, d4 = (idx & 15) * 4;
            *(float4*)(Ks + tok * FQ_P + d4) = *(const float4*)(kbase + (size_t)tok * (3 * C_) + d4);
            *(float4*)(Vs + tok * FV_P + d4) = *(const float4*)(vbase + (size_t)tok * (3 * C_) + d4);
        }
        __syncthreads();

        float sacc[4][4];
#pragma unroll
        for (int nt = 0; nt < 4; nt++)
#pragma unroll
            for (int q = 0; q < 4; q++) sacc[nt][q] = 0.f;
#pragma unroll
        for (int sl = 0; sl < 4; sl++) {
            int kb2 = sl * 16 + 2 * c_lo;
            uint32_t ah[4], al[4];
            const float* ab = Qs + (wm * 16 + r_lo) * FQ_P + kb2;
            split_pack(ab[0], ab[1], ah[0], al[0]);
            split_pack(ab[8 * FQ_P], ab[8 * FQ_P + 1], ah[1], al[1]);
            split_pack(ab[8], ab[9], ah[2], al[2]);
            split_pack(ab[8 * FQ_P + 8], ab[8 * FQ_P + 9], ah[3], al[3]);
#pragma unroll
            for (int nt = 0; nt < 4; nt++) {
                const float* bb = Ks + (wn * 32 + nt * 8 + r_lo) * FQ_P + kb2;
                uint32_t bh0, bl0, bh1, bl1;
                split_pack(bb[0], bb[1], bh0, bl0);
                split_pack(bb[8], bb[9], bh1, bl1);
                MMA_BF16(sacc[nt], ah[0], ah[1], ah[2], ah[3], bh0, bh1);
                MMA_BF16(sacc[nt], ah[0], ah[1], ah[2], ah[3], bl0, bl1);
                MMA_BF16(sacc[nt], al[0], al[1], al[2], al[3], bh0, bh1);
            }
        }
        bool diag = (kb == qb);
#pragma unroll
        for (int nt = 0; nt < 4; nt++)
#pragma unroll
            for (int q = 0; q < 4; q++) {
                int rloc = (q >= 2) ? row0 + 8 : row0;
                int cloc = wn * 32 + nt * 8 + 2 * c_lo + (q & 1);
                float v = sacc[nt][q] * 0.125f;
                if (diag && cloc > rloc) v = -1e30f;
                sacc[nt][q] = v;
            }
        float rm0 = -1e30f, rm1 = -1e30f;
#pragma unroll
        for (int nt = 0; nt < 4; nt++) {
            rm0 = fmaxf(rm0, fmaxf(sacc[nt][0], sacc[nt][1]));
            rm1 = fmaxf(rm1, fmaxf(sacc[nt][2], sacc[nt][3]));
        }
        rm0 = fmaxf(rm0, __shfl_xor_sync(0xffffffffu, rm0, 1));
        rm0 = fmaxf(rm0, __shfl_xor_sync(0xffffffffu, rm0, 2));
        rm1 = fmaxf(rm1, __shfl_xor_sync(0xffffffffu, rm1, 1));
        rm1 = fmaxf(rm1, __shfl_xor_sync(0xffffffffu, rm1, 2));
        if (c_lo == 0) {
            Wmax[wn * 64 + row0] = rm0;
            Wmax[wn * 64 + row0 + 8] = rm1;
        }
        __syncthreads();
        float mn0 = fmaxf(Mrow[row0],     fmaxf(Wmax[row0],     Wmax[64 + row0]));
        float mn1 = fmaxf(Mrow[row0 + 8], fmaxf(Wmax[row0 + 8], Wmax[64 + row0 + 8]));
        float rs0 = 0.f, rs1 = 0.f;
#pragma unroll
        for (int nt = 0; nt < 4; nt++) {
            float p0 = expf(sacc[nt][0] - mn0);
            float p1 = expf(sacc[nt][1] - mn0);
            float p2 = expf(sacc[nt][2] - mn1);
            float p3 = expf(sacc[nt][3] - mn1);
            rs0 += p0 + p1; rs1 += p2 + p3;
            int c = wn * 32 + nt * 8 + 2 * c_lo;
            float2 v0; v0.x = p0; v0.y = p1;
            float2 v1; v1.x = p2; v1.y = p3;
            *(float2*)(Ps + (wm * 16 + r_lo) * FP_P + c)       = v0;
            *(float2*)(Ps + (wm * 16 + r_lo + 8) * FP_P + c)   = v1;
        }
        rs0 += __shfl_xor_sync(0xffffffffu, rs0, 1);
        rs0 += __shfl_xor_sync(0xffffffffu, rs0, 2);
        rs1 += __shfl_xor_sync(0xffffffffu, rs1, 1);
        rs1 += __shfl_xor_sync(0xffffffffu, rs1, 2);
        if (c_lo == 0) {
            Wsum[wn * 64 + row0] = rs0;
            Wsum[wn * 64 + row0 + 8] = rs1;
        }
        __syncthreads();
        if (tid < 64) {
            int r = tid;
            float mold = Mrow[r];
            float mn = fmaxf(mold, fmaxf(Wmax[r], Wmax[64 + r]));
            float a = expf(mold - mn);
            Arow[r] = a;
            Lrow[r] = Lrow[r] * a + Wsum[r] + Wsum[64 + r];
            Mrow[r] = mn;
        }
        __syncthreads();
        float a0 = Arow[row0], a1 = Arow[row0 + 8];
#pragma unroll
        for (int nt = 0; nt < 4; nt++) {
            oacc[nt][0] *= a0; oacc[nt][1] *= a0;
            oacc[nt][2] *= a1; oacc[nt][3] *= a1;
        }
#pragma unroll
        for (int sl = 0; sl < 4; sl++) {
            int kb2 = sl * 16 + 2 * c_lo;
            uint32_t ah[4], al[4];
            const float* ab = Ps + (wm * 16 + r_lo) * FP_P + kb2;
            split_pack(ab[0], ab[1], ah[0], al[0]);
            split_pack(ab[8 * FP_P], ab[8 * FP_P + 1], ah[1], al[1]);
            split_pack(ab[8], ab[9], ah[2], al[2]);
            split_pack(ab[8 * FP_P + 8], ab[8 * FP_P + 9], ah[3], al[3]);
#pragma unroll
            for (int nt = 0; nt < 4; nt++) {
                const float* bb = Vs + kb2 * FV_P + wn * 32 + nt * 8 + r_lo;
                uint32_t bh0, bl0, bh1, bl1;
                split_pack(bb[0],          bb[FV_P],     bh0, bl0);
                split_pack(bb[8 * FV_P],   bb[9 * FV_P], bh1, bl1);
                MMA_BF16(oacc[nt], ah[0], ah[1], ah[2], ah[3], bh0, bh1);
                MMA_BF16(oacc[nt], ah[0], ah[1], ah[2], ah[3], bl0, bl1);
                MMA_BF16(oacc[nt], al[0], al[1], al[2], al[3], bh0, bh1);
            }
        }
    }

    float l0 = 1.0f / Lrow[row0], l1 = 1.0f / Lrow[row0 + 8];
#pragma unroll
    for (int nt = 0; nt < 4; nt++) {
        int col = wn * 32 + nt * 8 + 2 * c_lo;
        float2 v0; v0.x = oacc[nt][0] * l0; v0.y = oacc[nt][1] * l0;
        float2 v1; v1.x = oacc[nt][2] * l1; v1.y = oacc[nt][3] * l1;
        *(float2*)(out + (size_t)(b * T_ + q0 + row0) * C_ + h * HD_ + col)     = v0;
        *(float2*)(out + (size_t)(b * T_ + q0 + row0 + 8) * C_ + h * HD_ + col) = v1;
    }
}

// ---------------- routing: warp-parallel per-expert prefix + inverse map ----------
__global__ void route_kernel(const int* __restrict__ top, int* __restrict__ slot,
                             int* __restrict__ inv) {
    int e = threadIdx.x >> 5, lane = threadIdx.x & 31;
    for (int i = lane; i < CAP; i += 32) inv[e * CAP + i] = 0;   // safe default row
    int cnt = 0;
    for (int base = 0; base < NTOK; base += 32) {
        int n = base + lane;
        int t0 = top[2 * n], t1 = top[2 * n + 1];
        bool m = (t0 == e) || (t1 == e);
        unsigned ball = __ballot_sync(0xffffffffu, m);
        if (m) {
            int pos = cnt + __popc(ball & ((1u << lane) - 1));
            int s = (pos < CAP) ? pos : -1;
            if (s >= 0) inv[e * CAP + s] = n;
            if (t0 == e) slot[2 * n] = s; else slot[2 * n + 1] = s;
        }
        cnt += __popc(ball);
    }
}

// ---------------- combine + residual ----------------
__global__ void combine_kernel(const float* __restrict__ y, const float* __restrict__ gates,
                               const int* __restrict__ top, const int* __restrict__ slot,
                               float* __restrict__ x) {
    int n = blockIdx.x;
    int e0 = top[2 * n], e1 = top[2 * n + 1];
    int s0 = slot[2 * n], s1 = slot[2 * n + 1];
    float w0 = (s0 >= 0) ? gates[(size_t)n * E_ + e0] : 0.f;
    float w1 = (s1 >= 0) ? gates[(size_t)n * E_ + e1] : 0.f;
    const float* y0 = y + ((size_t)e0 * CAP + (s0 >= 0 ? s0 : 0)) * C_;
    const float* y1 = y + ((size_t)e1 * CAP + (s1 >= 0 ? s1 : 0)) * C_;
    float* xr = x + (size_t)n * C_;
    for (int c = threadIdx.x; c < C_; c += 256)
        xr[c] += w0 * y0[c] + w1 * y1[c];
}

// ---------------- launch ----------------
extern "C" void kernel_launch(void* const* d_in, const int* in_sizes, int n_in,
                              void* d_out, int out_size) {
    const int*   idx     = (const int*)  d_in[0];
    const float* tok_emb = (const float*)d_in[1];
    const float* ln1_g   = (const float*)d_in[2];
    const float* ln1_b   = (const float*)d_in[3];
    const float* qkv_w   = (const float*)d_in[4];
    const float* proj_w  = (const float*)d_in[5];
    const float* ln2_g   = (const float*)d_in[6];
    const float* ln2_b   = (const float*)d_in[7];
    const float* gate_w  = (const float*)d_in[8];
    const float* w1      = (const float*)d_in[9];
    const float* b1      = (const float*)d_in[10];
    const float* w2      = (const float*)d_in[11];
    const float* b2      = (const float*)d_in[12];
    const float* lnf_g   = (const float*)d_in[13];
    const float* lnf_b   = (const float*)d_in[14];
    const float* lm_head = (const float*)d_in[15];
    float* out = (float*)d_out;

    float *x, *ln, *qkv, *attn, *gates, *hbuf, *ybuf;
    int *top, *slot, *inv;
    cudaGetSymbolAddress((void**)&x,     g_x);
    cudaGetSymbolAddress((void**)&ln,    g_ln);
    cudaGetSymbolAddress((void**)&qkv,   g_qkv);
    cudaGetSymbolAddress((void**)&attn,  g_attn);
    cudaGetSymbolAddress((void**)&gates, g_gates);
    cudaGetSymbolAddress((void**)&top,   g_top);
    cudaGetSymbolAddress((void**)&slot,  g_slot);
    cudaGetSymbolAddress((void**)&inv,   g_inv);
    cudaGetSymbolAddress((void**)&hbuf,  g_hbuf);
    cudaGetSymbolAddress((void**)&ybuf,  g_ybuf);

    cudaFuncSetAttribute((const void*)mm_mma_kernel<128, 1, false>, cudaFuncAttributeMaxDynamicSharedMemorySize, SM_128);
    cudaFuncSetAttribute((const void*)mm_mma_kernel<128, 2, false>, cudaFuncAttributeMaxDynamicSharedMemorySize, SM_128);
    cudaFuncSetAttribute((const void*)mm_mma_kernel<64, 1, false>,  cudaFuncAttributeMaxDynamicSharedMemorySize, SM_64);
    cudaFuncSetAttribute((const void*)mm_mma_kernel<64, 2, false>,  cudaFuncAttributeMaxDynamicSharedMemorySize, SM_64);
    cudaFuncSetAttribute((const void*)mm_mma_kernel<64, 1, true>,   cudaFuncAttributeMaxDynamicSharedMemorySize, SM_64);
    cudaFuncSetAttribute((const void*)mm_mma_kernel<64, 2, true>,   cudaFuncAttributeMaxDynamicSharedMemorySize, SM_64);
    cudaFuncSetAttribute((const void*)flash_attn_kernel, cudaFuncAttributeMaxDynamicSharedMemorySize, FA_SMEM);

    embed_kernel<<<NTOK * C_ / 256, 256>>>(idx, tok_emb, x);

    for (int l = 0; l < L_; l++) {
        // --- attention (routing-critical -> bf16x3; MT=128) ---
        ln_kernel<<<NTOK, 256>>>(x, ln1_g + (size_t)l * C_, ln1_b + (size_t)l * C_, ln);
        mm_mma_kernel<128, 1, false><<<dim3(NTOK / 128, 3 * C_ / 128, 1), 256, SM_128>>>(
            ln, qkv_w + (size_t)l * C_ * 3 * C_, qkv, nullptr, nullptr,
            NTOK, 3 * C_, C_, 0, 0, 0, 0, 0, 3);
        rope_kernel<<<(NTOK * H_ * (HD_ / 2) + 255) / 256, 256>>>(qkv);
        flash_attn_kernel<<<dim3(T_ / 64, B_ * H_), 256, FA_SMEM>>>(qkv, attn);
        mm_mma_kernel<128, 1, false><<<dim3(NTOK / 128, C_ / 128, 1), 256, SM_128>>>(
            attn, proj_w + (size_t)l * C_ * C_, x, nullptr, nullptr,
            NTOK, C_, C_, 0, 0, 0, 0, 1, 3);  // += residual

        // --- MoE (fused ln+gate; w1 gathers token rows directly from ln) ---
        lngate_kernel<<<NTOK, 256>>>(x, ln2_g + (size_t)l * C_, ln2_b + (size_t)l * C_,
                                     gate_w + (size_t)l * C_ * E_, ln, gates, top);
        route_kernel<<<1, 256>>>(top, slot, inv);
        if (l < L_ - 1) {
            mm_mma_kernel<64, 1, true><<<dim3(CAP / 64, FF_ / 128, E_), 256, SM_64>>>(
                ln, w1 + (size_t)l * E_ * C_ * FF_, hbuf, b1 + (size_t)l * E_ * FF_, inv,
                CAP, FF_, C_, 0, (long)C_ * FF_, (long)CAP * FF_, (long)FF_, 2, 3);
            mm_mma_kernel<64, 1, false><<<dim3(CAP / 64, C_ / 128, E_), 256, SM_64>>>(
                hbuf, w2 + (size_t)l * E_ * FF_ * C_, ybuf, b2 + (size_t)l * E_ * C_, nullptr,
                CAP, C_, FF_, (long)CAP * FF_, (long)FF_ * C_, (long)CAP * C_, (long)C_, 3, 3);
        } else {
            mm_mma_kernel<64, 2, true><<<dim3(CAP / 64, FF_ / 128, E_), 256, SM_64>>>(
                ln, w1 + (size_t)l * E_ * C_ * FF_, hbuf, b1 + (size_t)l * E_ * FF_, inv,
                CAP, FF_, C_, 0, (long)C_ * FF_, (long)CAP * FF_, (long)FF_, 2, 1);
            mm_mma_kernel<64, 2, false><<<dim3(CAP / 64, C_ / 128, E_), 256, SM_64>>>(
                hbuf, w2 + (size_t)l * E_ * FF_ * C_, ybuf, b2 + (size_t)l * E_ * C_, nullptr,
                CAP, C_, FF_, (long)CAP * FF_, (long)FF_ * C_, (long)CAP * C_, (long)C_, 3, 1);
        }
        combine_kernel<<<NTOK, 256>>>(ybuf, gates, top, slot, x);
    }

    ln_kernel<<<NTOK, 256>>>(x, lnf_g, lnf_b, ln);
    mm_mma_kernel<128, 2, false><<<dim3(NTOK / 128, V_ / 128, 1), 256, SM_128>>>(
        ln, lm_head, out, nullptr, nullptr, NTOK, V_, C_, 0, 0, 0, 0, 0, 1);
}

// round 15
// speedup vs baseline: 1.1725x; 1.0809x over previous
#include <cuda_runtime.h>
#include <cuda_bf16.h>
#include <cuda_fp16.h>
#include <math.h>
#include <stdint.h>

#define B_   2
#define T_   1024
#define C_   1024
#define H_   16
#define HD_  64
#define L_   2
#define E_   8
#define FF_  4096
#define V_   32000
#define NTOK (B_ * T_)
#define CAP  320

// ---------------- scratch ----------------
__device__ float g_x[NTOK * C_];
__device__ float g_ln[NTOK * C_];
__device__ float g_qkv[NTOK * 3 * C_];
__device__ float g_attn[NTOK * C_];
__device__ float g_gates[NTOK * E_];
__device__ int   g_top[NTOK * 2];
__device__ int   g_slot[NTOK * 2];
__device__ int   g_inv[E_ * CAP];
__device__ float g_hbuf[E_ * CAP * FF_];
__device__ float g_ybuf[E_ * CAP * C_];

// ---------------- helpers ----------------
__device__ __forceinline__ float warp_sum(float v) {
#pragma unroll
    for (int o = 16; o; o >>= 1) v += __shfl_xor_sync(0xffffffffu, v, o);
    return v;
}
__device__ __forceinline__ float gelu_exact(float v) {
    return 0.5f * v * (1.0f + erff(v * 0.70710678118654752f));
}
__device__ __forceinline__ float bf_hi(float v) {
    return __bfloat162float(__float2bfloat16(v));
}
__device__ __forceinline__ uint32_t pack_bf2(float a, float b) {
    uint32_t r;
    asm("cvt.rn.bf16x2.f32 %0, %1, %2;" : "=r"(r) : "f"(b), "f"(a));
    return r;
}
__device__ __forceinline__ uint32_t pack_f16(float a, float b) {
    uint32_t r;
    asm("cvt.rn.f16x2.f32 %0, %1, %2;" : "=r"(r) : "f"(b), "f"(a));
    return r;
}
__device__ __forceinline__ void split_pack(float x0, float x1, uint32_t& hi, uint32_t& lo) {
    float h0 = bf_hi(x0), h1 = bf_hi(x1);
    hi = pack_bf2(h0, h1);
    lo = pack_bf2(x0 - h0, x1 - h1);
}

#define MMA_BF16(accp, a0, a1, a2, a3, b0, b1)                                  \
    asm volatile(                                                               \
        "mma.sync.aligned.m16n8k16.row.col.f32.bf16.bf16.f32 "                  \
        "{%0,%1,%2,%3}, {%4,%5,%6,%7}, {%8,%9}, {%0,%1,%2,%3};"                 \
        : "+f"((accp)[0]), "+f"((accp)[1]), "+f"((accp)[2]), "+f"((accp)[3])    \
        : "r"(a0), "r"(a1), "r"(a2), "r"(a3), "r"(b0), "r"(b1))

#define MMA_F16(accp, a0, a1, a2, a3, b0, b1)                                   \
    asm volatile(                                                               \
        "mma.sync.aligned.m16n8k16.row.col.f32.f16.f16.f32 "                    \
        "{%0,%1,%2,%3}, {%4,%5,%6,%7}, {%8,%9}, {%0,%1,%2,%3};"                 \
        : "+f"((accp)[0]), "+f"((accp)[1]), "+f"((accp)[2]), "+f"((accp)[3])    \
        : "r"(a0), "r"(a1), "r"(a2), "r"(a3), "r"(b0), "r"(b1))

// ======== tensor-core GEMM: pre-split packed smem planes ========
// MODE 1: bf16x3 hi/lo planes (routing-critical; rn splits computed ONCE at fill)
// MODE 2: fp16 single plane (non-routing)
// A plane pitch 20 u32/kpair-row (banks 20r+c bijective); B plane pitch 136 u32
// (banks 8c+r bijective). Inner loop = pure LDS.32 + mma.
// GATHER: A row m read from gidx[z*CAP + m] (MoE dispatch).
#define PA_ 20
#define PB_ 136

template<int MT, int MODE, bool GATHER>
__global__ void __launch_bounds__(256, MT == 64 ? 2 : 1)
mm_mma_kernel(const float* __restrict__ A, const float* __restrict__ B,
              float* __restrict__ C, const float* __restrict__ bias,
              const int* __restrict__ gidx,
              int Mv, int N, int K,
              long sA, long sB, long sC, long sBias, int ep)
{
    constexpr int MTW   = MT / 32;
    constexpr int AIT   = MT / 32;
    constexpr int APL   = MT * PA_;         // u32 per A plane
    constexpr int BPL   = 16 * PB_;         // u32 per B plane
    constexpr int NPLA  = (MODE == 1) ? 2 : 1;
    constexpr int BUFSZ = NPLA * (APL + BPL);
    extern __shared__ uint32_t smu[];
    int tid = threadIdx.x, lane = tid & 31, wid = tid >> 5;
    int wm = wid & 1, wn = wid >> 1;
    int r_lo = lane >> 2, c_lo = lane & 3;
    int z = blockIdx.z;
    A += (long)z * sA; B += (long)z * sB; C += (long)z * sC;
    const float* bp = bias ? bias + (long)z * sBias : nullptr;
    int m0 = blockIdx.x * MT, n0 = blockIdx.y * 128;

    int grow[AIT];
    if (GATHER) {
#pragma unroll
        for (int it = 0; it < AIT; it++)
            grow[it] = gidx[z * CAP + m0 + ((tid + it * 256) >> 3)];
    }

    float acc[MTW][4][4];
#pragma unroll
    for (int i = 0; i < MTW; i++)
#pragma unroll
        for (int j = 0; j < 4; j++)
#pragma unroll
            for (int k = 0; k < 4; k++) acc[i][j][k] = 0.f;

    float4 pa[AIT];
    float2 pb0[4], pb1[4];

    auto prefetch = [&](int i) {
        int k0 = i << 5;
#pragma unroll
        for (int it = 0; it < AIT; it++) {
            int idx = tid + it * 256;
            int m = idx >> 3, f4 = idx & 7;
            long arow = GATHER ? (long)grow[it] : (long)(m0 + m);
            pa[it] = *(const float4*)(A + (size_t)arow * K + k0 + f4 * 4);
        }
#pragma unroll
        for (int it = 0; it < 4; it++) {
            int idx = tid + it * 256;
            int kp = idx >> 6, n2 = idx & 63;
            const float* bptr = B + (size_t)(k0 + 2 * kp) * N + n0 + 2 * n2;
            pb0[it] = *(const float2*)bptr;
            pb1[it] = *(const float2*)(bptr + N);
        }
    };
    auto cstore = [&](int s) {
        uint32_t* base = smu + s * BUFSZ;
        uint32_t* Ah = base;
        uint32_t* Al = base + APL;                       // only MODE 1
        uint32_t* Bh = base + NPLA * APL;
        uint32_t* Bl = Bh + BPL;                         // only MODE 1
#pragma unroll
        for (int it = 0; it < AIT; it++) {
            int idx = tid + it * 256;
            int m = idx >> 3, f4 = idx & 7;
            float4 v = pa[it];
            if constexpr (MODE == 1) {
                uint32_t h0, l0, h1, l1;
                split_pack(v.x, v.y, h0, l0);
                split_pack(v.z, v.w, h1, l1);
                *(uint2*)(Ah + m * PA_ + 2 * f4) = make_uint2(h0, h1);
                *(uint2*)(Al + m * PA_ + 2 * f4) = make_uint2(l0, l1);
            } else {
                *(uint2*)(Ah + m * PA_ + 2 * f4) =
                    make_uint2(pack_f16(v.x, v.y), pack_f16(v.z, v.w));
            }
        }
#pragma unroll
        for (int it = 0; it < 4; it++) {
            int idx = tid + it * 256;
            int kp = idx >> 6, n2 = idx & 63;
            float2 f0 = pb0[it], f1 = pb1[it];
            if constexpr (MODE == 1) {
                uint32_t h0, l0, h1, l1;
                split_pack(f0.x, f1.x, h0, l0);
                split_pack(f0.y, f1.y, h1, l1);
                *(uint2*)(Bh + kp * PB_ + 2 * n2) = make_uint2(h0, h1);
                *(uint2*)(Bl + kp * PB_ + 2 * n2) = make_uint2(l0, l1);
            } else {
                *(uint2*)(Bh + kp * PB_ + 2 * n2) =
                    make_uint2(pack_f16(f0.x, f1.x), pack_f16(f0.y, f1.y));
            }
        }
    };

    int nch = K >> 5;
    prefetch(0);
    cstore(0);
    __syncthreads();
    for (int i = 0; i < nch; i++) {
        if (i + 1 < nch) prefetch(i + 1);
        {
            uint32_t* base = smu + (i & 1) * BUFSZ;
            uint32_t* Ah = base;
            uint32_t* Al = base + APL;
            uint32_t* Bh = base + NPLA * APL;
            uint32_t* Bl = Bh + BPL;
#pragma unroll
            for (int ks = 0; ks < 2; ks++) {
                int kq = ks * 8 + c_lo;                 // kpair index
                if constexpr (MODE == 1) {
                    uint32_t ah[MTW][4], al[MTW][4], bh[4][2], bl[4][2];
#pragma unroll
                    for (int mt = 0; mt < MTW; mt++) {
                        int ro = (wm * (MT / 2) + mt * 16 + r_lo) * PA_ + kq;
                        ah[mt][0] = Ah[ro];
                        ah[mt][1] = Ah[ro + 8 * PA_];
                        ah[mt][2] = Ah[ro + 4];
                        ah[mt][3] = Ah[ro + 8 * PA_ + 4];
                        al[mt][0] = Al[ro];
                        al[mt][1] = Al[ro + 8 * PA_];
                        al[mt][2] = Al[ro + 4];
                        al[mt][3] = Al[ro + 8 * PA_ + 4];
                    }
#pragma unroll
                    for (int nt = 0; nt < 4; nt++) {
                        int bo = kq * PB_ + wn * 32 + nt * 8 + r_lo;
                        bh[nt][0] = Bh[bo];
                        bh[nt][1] = Bh[bo + 4 * PB_];
                        bl[nt][0] = Bl[bo];
                        bl[nt][1] = Bl[bo + 4 * PB_];
                    }
#pragma unroll
                    for (int mt = 0; mt < MTW; mt++)
#pragma unroll
                        for (int nt = 0; nt < 4; nt++) {
                            MMA_BF16(acc[mt][nt], ah[mt][0], ah[mt][1], ah[mt][2], ah[mt][3],
                                     bh[nt][0], bh[nt][1]);
                            MMA_BF16(acc[mt][nt], ah[mt][0], ah[mt][1], ah[mt][2], ah[mt][3],
                                     bl[nt][0], bl[nt][1]);
                            MMA_BF16(acc[mt][nt], al[mt][0], al[mt][1], al[mt][2], al[mt][3],
                                     bh[nt][0], bh[nt][1]);
                        }
                } else {
                    uint32_t ah[MTW][4], bh[4][2];
#pragma unroll
                    for (int mt = 0; mt < MTW; mt++) {
                        int ro = (wm * (MT / 2) + mt * 16 + r_lo) * PA_ + kq;
                        ah[mt][0] = Ah[ro];
                        ah[mt][1] = Ah[ro + 8 * PA_];
                        ah[mt][2] = Ah[ro + 4];
                        ah[mt][3] = Ah[ro + 8 * PA_ + 4];
                    }
#pragma unroll
                    for (int nt = 0; nt < 4; nt++) {
                        int bo = kq * PB_ + wn * 32 + nt * 8 + r_lo;
                        bh[nt][0] = Bh[bo];
                        bh[nt][1] = Bh[bo + 4 * PB_];
                    }
#pragma unroll
                    for (int mt = 0; mt < MTW; mt++)
#pragma unroll
                        for (int nt = 0; nt < 4; nt++)
                            MMA_F16(acc[mt][nt], ah[mt][0], ah[mt][1], ah[mt][2], ah[mt][3],
                                    bh[nt][0], bh[nt][1]);
                }
            }
        }
        __syncthreads();
        if (i + 1 < nch) {
            cstore((i + 1) & 1);
            __syncthreads();
        }
    }

    int rbase = m0 + wm * (MT / 2) + (lane >> 2);
    int cbase = n0 + wn * 32 + (lane & 3) * 2;
#pragma unroll
    for (int mt = 0; mt < MTW; mt++) {
#pragma unroll
        for (int half = 0; half < 2; half++) {
            int row = rbase + mt * 16 + half * 8;
            if (row >= Mv) continue;
#pragma unroll
            for (int nt = 0; nt < 4; nt++) {
                int col = cbase + nt * 8;
                float x0 = acc[mt][nt][half * 2 + 0];
                float x1 = acc[mt][nt][half * 2 + 1];
                if (ep == 2)      { x0 = gelu_exact(x0 + bp[col]); x1 = gelu_exact(x1 + bp[col + 1]); }
                else if (ep == 3) { x0 += bp[col]; x1 += bp[col + 1]; }
                float* cp = C + (size_t)row * N + col;
                if (ep == 1) { x0 += cp[0]; x1 += cp[1]; }
                float2 o; o.x = x0; o.y = x1;
                *(float2*)cp = o;
            }
        }
    }
}
#define SMSZ(MT, NPLA) (2 * (NPLA) * ((MT) * PA_ + 16 * PB_) * 4)
#define SM_128_BF SMSZ(128, 2)
#define SM_128_HF SMSZ(128, 1)
#define SM_64_BF  SMSZ(64, 2)
#define SM_64_HF  SMSZ(64, 1)

// ---------------- embedding gather ----------------
__global__ void embed_kernel(const int* __restrict__ idx, const float* __restrict__ emb,
                             float* __restrict__ x) {
    int i = blockIdx.x * 256 + threadIdx.x;
    int n = i >> 10, c = i & 1023;
    x[i] = emb[(size_t)idx[n] * C_ + c];
}

// ---------------- layernorm ----------------
__global__ void ln_kernel(const float* __restrict__ x, const float* __restrict__ g,
                          const float* __restrict__ b, float* __restrict__ out) {
    int row = blockIdx.x;
    const float* xr = x + (size_t)row * C_;
    float s = 0.f, s2 = 0.f;
    for (int c = threadIdx.x; c < C_; c += 256) { float v = xr[c]; s += v; s2 += v * v; }
    __shared__ float sh1[8], sh2[8], shm[2];
    int lane = threadIdx.x & 31, w = threadIdx.x >> 5;
    s = warp_sum(s); s2 = warp_sum(s2);
    if (!lane) { sh1[w] = s; sh2[w] = s2; }
    __syncthreads();
    if (threadIdx.x == 0) {
        float S = 0.f, S2 = 0.f;
        for (int i = 0; i < 8; i++) { S += sh1[i]; S2 += sh2[i]; }
        float mean = S * (1.0f / C_);
        float var  = S2 * (1.0f / C_) - mean * mean;
        shm[0] = mean; shm[1] = rsqrtf(var + 1e-5f);
    }
    __syncthreads();
    float mean = shm[0], inv = shm[1];
    float* orow = out + (size_t)row * C_;
    for (int c = threadIdx.x; c < C_; c += 256)
        orow[c] = (xr[c] - mean) * inv * g[c] + b[c];
}

// ---------------- fused layernorm + gate (MoE path) ----------------
__global__ void lngate_kernel(const float* __restrict__ x, const float* __restrict__ g,
                              const float* __restrict__ b, const float* __restrict__ gw,
                              float* __restrict__ out, float* __restrict__ gates,
                              int* __restrict__ top) {
    int row = blockIdx.x;
    const float* xr = x + (size_t)row * C_;
    __shared__ float sh1[8], sh2[8], shm[2], lnrow[C_], sl[E_];
    int lane = threadIdx.x & 31, w = threadIdx.x >> 5;
    float s = 0.f, s2 = 0.f;
    for (int c = threadIdx.x; c < C_; c += 256) { float v = xr[c]; s += v; s2 += v * v; }
    s = warp_sum(s); s2 = warp_sum(s2);
    if (!lane) { sh1[w] = s; sh2[w] = s2; }
    __syncthreads();
    if (threadIdx.x == 0) {
        float S = 0.f, S2 = 0.f;
        for (int i = 0; i < 8; i++) { S += sh1[i]; S2 += sh2[i]; }
        float mean = S * (1.0f / C_);
        float var  = S2 * (1.0f / C_) - mean * mean;
        shm[0] = mean; shm[1] = rsqrtf(var + 1e-5f);
    }
    __syncthreads();
    float mean = shm[0], inv = shm[1];
    float* orow = out + (size_t)row * C_;
    for (int c = threadIdx.x; c < C_; c += 256) {
        float v = (xr[c] - mean) * inv * g[c] + b[c];
        lnrow[c] = v;
        orow[c] = v;
    }
    __syncthreads();
    float acc = 0.f;
    for (int c = lane; c < C_; c += 32) acc += lnrow[c] * gw[(size_t)c * E_ + w];
    acc = warp_sum(acc);
    if (!lane) sl[w] = acc;
    __syncthreads();
    if (threadIdx.x == 0) {
        float p[E_];
        float m = sl[0];
        for (int e = 1; e < E_; e++) m = fmaxf(m, sl[e]);
        float ssum = 0.f;
        for (int e = 0; e < E_; e++) { p[e] = expf(sl[e] - m); ssum += p[e]; }
        float invs = 1.0f / ssum;
        for (int e = 0; e < E_; e++) { p[e] *= invs; gates[(size_t)row * E_ + e] = p[e]; }
        int i0 = 0;
        for (int e = 1; e < E_; e++) if (p[e] > p[i0]) i0 = e;
        int i1 = -1;
        for (int e = 0; e < E_; e++) {
            if (e == i0) continue;
            if (i1 < 0 || p[e] > p[i1]) i1 = e;
        }
        top[2 * row] = i0; top[2 * row + 1] = i1;
    }
}

// ---------------- RoPE ----------------
__global__ void rope_kernel(float* __restrict__ qkv) {
    int i = blockIdx.x * 256 + threadIdx.x;
    if (i >= NTOK * H_ * (HD_ / 2)) return;
    int j = i & 31;
    int h = (i >> 5) & 15;
    int n = i >> 9;
    int t = n & (T_ - 1);
    float e = (float)(2 * j) / (float)HD_;
    float invf = 1.0f / powf(10000.0f, e);
    float ang = (float)t * invf;
    float s = sinf(ang), c = cosf(ang);
    float* base = qkv + (size_t)n * (3 * C_) + h * (3 * HD_);
    float q1 = base[j],      q2 = base[j + 32];
    base[j]      = q1 * c - q2 * s;
    base[j + 32] = q1 * s + q2 * c;
    float k1 = base[64 + j], k2 = base[64 + j + 32];
    base[64 + j]      = k1 * c - k2 * s;
    base[64 + j + 32] = k1 * s + k2 * c;
}

// ---------------- tensor-core flash attention (bf16x3 QK and PV) ----------------
#define FQ_P 72
#define FV_P 68
#define FP_P 72
#define FA_QS   0
#define FA_KS   (64 * FQ_P)
#define FA_VS   (FA_KS + 64 * FQ_P)
#define FA_PS   (FA_VS + 64 * FV_P)
#define FA_WMAX (FA_PS + 64 * FP_P)
#define FA_WSUM (FA_WMAX + 128)
#define FA_MROW (FA_WSUM + 128)
#define FA_LROW (FA_MROW + 64)
#define FA_AROW (FA_LROW + 64)
#define FA_SMEM ((FA_AROW + 64) * 4)

__global__ void __launch_bounds__(256, 1)
flash_attn_kernel(const float* __restrict__ qkv, float* __restrict__ out) {
    extern __shared__ float fs[];
    float* Qs = fs + FA_QS;
    float* Ks = fs + FA_KS;
    float* Vs = fs + FA_VS;
    float* Ps = fs + FA_PS;
    float* Wmax = fs + FA_WMAX;
    float* Wsum = fs + FA_WSUM;
    float* Mrow = fs + FA_MROW;
    float* Lrow = fs + FA_LROW;
    float* Arow = fs + FA_AROW;
    int bh = blockIdx.y; int b = bh >> 4, h = bh & 15;
    int qb = (int)gridDim.x - 1 - (int)blockIdx.x;
    int q0 = qb * 64;
    int tid = threadIdx.x, lane = tid & 31, wid = tid >> 5;
    int wm = wid & 3, wn = wid >> 2;
    int r_lo = lane >> 2, c_lo = lane & 3;
    int row0 = wm * 16 + r_lo;

    const float* qbase = qkv + (size_t)(b * T_ + q0) * (3 * C_) + h * (3 * HD_);
#pragma unroll
    for (int r = 0; r < 4; r++) {
        int idx = tid + r * 256;
        int tok = idx >> 4, d4 = (idx & 15) * 4;
        *(float4*)(Qs + tok * FQ_P + d4) = *(const float4*)(qbase + (size_t)tok * (3 * C_) + d4);
    }
    if (tid < 64) { Mrow[tid] = -1e30f; Lrow[tid] = 0.f; }

    float oacc[4][4];
#pragma unroll
    for (int nt = 0; nt < 4; nt++)
#pragma unroll
        for (int q = 0; q < 4; q++) oacc[nt][q] = 0.f;

    for (int kb = 0; kb <= qb; kb++) {
        int k0 = kb * 64;
        __syncthreads();
        const float* kbase = qkv + (size_t)(b * T_ + k0) * (3 * C_) + h * (3 * HD_) + HD_;
        const float* vbase = kbase + HD_;
#pragma unroll
        for (int r = 0; r < 4; r++) {
            int idx = tid + r * 256;
            int tok = idx >> 4, d4 = (idx & 15) * 4;
            *(float4*)(Ks + tok * FQ_P + d4) = *(const float4*)(kbase + (size_t)tok * (3 * C_) + d4);
            *(float4*)(Vs + tok * FV_P + d4) = *(const float4*)(vbase + (size_t)tok * (3 * C_) + d4);
        }
        __syncthreads();

        float sacc[4][4];
#pragma unroll
        for (int nt = 0; nt < 4; nt++)
#pragma unroll
            for (int q = 0; q < 4; q++) sacc[nt][q] = 0.f;
#pragma unroll
        for (int sl = 0; sl < 4; sl++) {
            int kb2 = sl * 16 + 2 * c_lo;
            uint32_t ah[4], al[4];
            const float* ab = Qs + (wm * 16 + r_lo) * FQ_P + kb2;
            split_pack(ab[0], ab[1], ah[0], al[0]);
            split_pack(ab[8 * FQ_P], ab[8 * FQ_P + 1], ah[1], al[1]);
            split_pack(ab[8], ab[9], ah[2], al[2]);
            split_pack(ab[8 * FQ_P + 8], ab[8 * FQ_P + 9], ah[3], al[3]);
#pragma unroll
            for (int nt = 0; nt < 4; nt++) {
                const float* bb = Ks + (wn * 32 + nt * 8 + r_lo) * FQ_P + kb2;
                uint32_t bh0, bl0, bh1, bl1;
                split_pack(bb[0], bb[1], bh0, bl0);
                split_pack(bb[8], bb[9], bh1, bl1);
                MMA_BF16(sacc[nt], ah[0], ah[1], ah[2], ah[3], bh0, bh1);
                MMA_BF16(sacc[nt], ah[0], ah[1], ah[2], ah[3], bl0, bl1);
                MMA_BF16(sacc[nt], al[0], al[1], al[2], al[3], bh0, bh1);
            }
        }
        bool diag = (kb == qb);
#pragma unroll
        for (int nt = 0; nt < 4; nt++)
#pragma unroll
            for (int q = 0; q < 4; q++) {
                int rloc = (q >= 2) ? row0 + 8 : row0;
                int cloc = wn * 32 + nt * 8 + 2 * c_lo + (q & 1);
                float v = sacc[nt][q] * 0.125f;
                if (diag && cloc > rloc) v = -1e30f;
                sacc[nt][q] = v;
            }
        float rm0 = -1e30f, rm1 = -1e30f;
#pragma unroll
        for (int nt = 0; nt < 4; nt++) {
            rm0 = fmaxf(rm0, fmaxf(sacc[nt][0], sacc[nt][1]));
            rm1 = fmaxf(rm1, fmaxf(sacc[nt][2], sacc[nt][3]));
        }
        rm0 = fmaxf(rm0, __shfl_xor_sync(0xffffffffu, rm0, 1));
        rm0 = fmaxf(rm0, __shfl_xor_sync(0xffffffffu, rm0, 2));
        rm1 = fmaxf(rm1, __shfl_xor_sync(0xffffffffu, rm1, 1));
        rm1 = fmaxf(rm1, __shfl_xor_sync(0xffffffffu, rm1, 2));
        if (c_lo == 0) {
            Wmax[wn * 64 + row0] = rm0;
            Wmax[wn * 64 + row0 + 8] = rm1;
        }
        __syncthreads();
        float mn0 = fmaxf(Mrow[row0],     fmaxf(Wmax[row0],     Wmax[64 + row0]));
        float mn1 = fmaxf(Mrow[row0 + 8], fmaxf(Wmax[row0 + 8], Wmax[64 + row0 + 8]));
        float rs0 = 0.f, rs1 = 0.f;
#pragma unroll
        for (int nt = 0; nt < 4; nt++) {
            float p0 = expf(sacc[nt][0] - mn0);
            float p1 = expf(sacc[nt][1] - mn0);
            float p2 = expf(sacc[nt][2] - mn1);
            float p3 = expf(sacc[nt][3] - mn1);
            rs0 += p0 + p1; rs1 += p2 + p3;
            int c = wn * 32 + nt * 8 + 2 * c_lo;
            float2 v0; v0.x = p0; v0.y = p1;
            float2 v1; v1.x = p2; v1.y = p3;
            *(float2*)(Ps + (wm * 16 + r_lo) * FP_P + c)       = v0;
            *(float2*)(Ps + (wm * 16 + r_lo + 8) * FP_P + c)   = v1;
        }
        rs0 += __shfl_xor_sync(0xffffffffu, rs0, 1);
        rs0 += __shfl_xor_sync(0xffffffffu, rs0, 2);
        rs1 += __shfl_xor_sync(0xffffffffu, rs1, 1);
        rs1 += __shfl_xor_sync(0xffffffffu, rs1, 2);
        if (c_lo == 0) {
            Wsum[wn * 64 + row0] = rs0;
            Wsum[wn * 64 + row0 + 8] = rs1;
        }
        __syncthreads();
        if (tid < 64) {
            int r = tid;
            float mold = Mrow[r];
            float mn = fmaxf(mold, fmaxf(Wmax[r], Wmax[64 + r]));
            float a = expf(mold - mn);
            Arow[r] = a;
            Lrow[r] = Lrow[r] * a + Wsum[r] + Wsum[64 + r];
            Mrow[r] = mn;
        }
        __syncthreads();
        float a0 = Arow[row0], a1 = Arow[row0 + 8];
#pragma unroll
        for (int nt = 0; nt < 4; nt++) {
            oacc[nt][0] *= a0; oacc[nt][1] *= a0;
            oacc[nt][2] *= a1; oacc[nt][3] *= a1;
        }
#pragma unroll
        for (int sl = 0; sl < 4; sl++) {
            int kb2 = sl * 16 + 2 * c_lo;
            uint32_t ah[4], al[4];
            const float* ab = Ps + (wm * 16 + r_lo) * FP_P + kb2;
            split_pack(ab[0], ab[1], ah[0], al[0]);
            split_pack(ab[8 * FP_P], ab[8 * FP_P + 1], ah[1], al[1]);
            split_pack(ab[8], ab[9], ah[2], al[2]);
            split_pack(ab[8 * FP_P + 8], ab[8 * FP_P + 9], ah[3], al[3]);
#pragma unroll
            for (int nt = 0; nt < 4; nt++) {
                const float* bb = Vs + kb2 * FV_P + wn * 32 + nt * 8 + r_lo;
                uint32_t bh0, bl0, bh1, bl1;
                split_pack(bb[0],          bb[FV_P],     bh0, bl0);
                split_pack(bb[8 * FV_P],   bb[9 * FV_P], bh1, bl1);
                MMA_BF16(oacc[nt], ah[0], ah[1], ah[2], ah[3], bh0, bh1);
                MMA_BF16(oacc[nt], ah[0], ah[1], ah[2], ah[3], bl0, bl1);
                MMA_BF16(oacc[nt], al[0], al[1], al[2], al[3], bh0, bh1);
            }
        }
    }

    float l0 = 1.0f / Lrow[row0], l1 = 1.0f / Lrow[row0 + 8];
#pragma unroll
    for (int nt = 0; nt < 4; nt++) {
        int col = wn * 32 + nt * 8 + 2 * c_lo;
        float2 v0; v0.x = oacc[nt][0] * l0; v0.y = oacc[nt][1] * l0;
        float2 v1; v1.x = oacc[nt][2] * l1; v1.y = oacc[nt][3] * l1;
        *(float2*)(out + (size_t)(b * T_ + q0 + row0) * C_ + h * HD_ + col)     = v0;
        *(float2*)(out + (size_t)(b * T_ + q0 + row0 + 8) * C_ + h * HD_ + col) = v1;
    }
}

// ---------------- routing: warp-parallel per-expert prefix + inverse map ----------
__global__ void route_kernel(const int* __restrict__ top, int* __restrict__ slot,
                             int* __restrict__ inv) {
    int e = threadIdx.x >> 5, lane = threadIdx.x & 31;
    for (int i = lane; i < CAP; i += 32) inv[e * CAP + i] = 0;
    int cnt = 0;
    for (int base = 0; base < NTOK; base += 32) {
        int n = base + lane;
        int t0 = top[2 * n], t1 = top[2 * n + 1];
        bool m = (t0 == e) || (t1 == e);
        unsigned ball = __ballot_sync(0xffffffffu, m);
        if (m) {
            int pos = cnt + __popc(ball & ((1u << lane) - 1));
            int s = (pos < CAP) ? pos : -1;
            if (s >= 0) inv[e * CAP + s] = n;
            if (t0 == e) slot[2 * n] = s; else slot[2 * n + 1] = s;
        }
        cnt += __popc(ball);
    }
}

// ---------------- combine + residual ----------------
__global__ void combine_kernel(const float* __restrict__ y, const float* __restrict__ gates,
                               const int* __restrict__ top, const int* __restrict__ slot,
                               float* __restrict__ x) {
    int n = blockIdx.x;
    int e0 = top[2 * n], e1 = top[2 * n + 1];
    int s0 = slot[2 * n], s1 = slot[2 * n + 1];
    float w0 = (s0 >= 0) ? gates[(size_t)n * E_ + e0] : 0.f;
    float w1 = (s1 >= 0) ? gates[(size_t)n * E_ + e1] : 0.f;
    const float* y0 = y + ((size_t)e0 * CAP + (s0 >= 0 ? s0 : 0)) * C_;
    const float* y1 = y + ((size_t)e1 * CAP + (s1 >= 0 ? s1 : 0)) * C_;
    float* xr = x + (size_t)n * C_;
    for (int c = threadIdx.x; c < C_; c += 256)
        xr[c] += w0 * y0[c] + w1 * y1[c];
}

// ---------------- launch ----------------
extern "C" void kernel_launch(void* const* d_in, const int* in_sizes, int n_in,
                              void* d_out, int out_size) {
    const int*   idx     = (const int*)  d_in[0];
    const float* tok_emb = (const float*)d_in[1];
    const float* ln1_g   = (const float*)d_in[2];
    const float* ln1_b   = (const float*)d_in[3];
    const float* qkv_w   = (const float*)d_in[4];
    const float* proj_w  = (const float*)d_in[5];
    const float* ln2_g   = (const float*)d_in[6];
    const float* ln2_b   = (const float*)d_in[7];
    const float* gate_w  = (const float*)d_in[8];
    const float* w1      = (const float*)d_in[9];
    const float* b1      = (const float*)d_in[10];
    const float* w2      = (const float*)d_in[11];
    const float* b2      = (const float*)d_in[12];
    const float* lnf_g   = (const float*)d_in[13];
    const float* lnf_b   = (const float*)d_in[14];
    const float* lm_head = (const float*)d_in[15];
    float* out = (float*)d_out;

    float *x, *ln, *qkv, *attn, *gates, *hbuf, *ybuf;
    int *top, *slot, *inv;
    cudaGetSymbolAddress((void**)&x,     g_x);
    cudaGetSymbolAddress((void**)&ln,    g_ln);
    cudaGetSymbolAddress((void**)&qkv,   g_qkv);
    cudaGetSymbolAddress((void**)&attn,  g_attn);
    cudaGetSymbolAddress((void**)&gates, g_gates);
    cudaGetSymbolAddress((void**)&top,   g_top);
    cudaGetSymbolAddress((void**)&slot,  g_slot);
    cudaGetSymbolAddress((void**)&inv,   g_inv);
    cudaGetSymbolAddress((void**)&hbuf,  g_hbuf);
    cudaGetSymbolAddress((void**)&ybuf,  g_ybuf);

    cudaFuncSetAttribute((const void*)mm_mma_kernel<128, 1, false>, cudaFuncAttributeMaxDynamicSharedMemorySize, SM_128_BF);
    cudaFuncSetAttribute((const void*)mm_mma_kernel<128, 2, false>, cudaFuncAttributeMaxDynamicSharedMemorySize, SM_128_HF);
    cudaFuncSetAttribute((const void*)mm_mma_kernel<64, 1, false>,  cudaFuncAttributeMaxDynamicSharedMemorySize, SM_64_BF);
    cudaFuncSetAttribute((const void*)mm_mma_kernel<64, 2, false>,  cudaFuncAttributeMaxDynamicSharedMemorySize, SM_64_HF);
    cudaFuncSetAttribute((const void*)mm_mma_kernel<64, 1, true>,   cudaFuncAttributeMaxDynamicSharedMemorySize, SM_64_BF);
    cudaFuncSetAttribute((const void*)mm_mma_kernel<64, 2, true>,   cudaFuncAttributeMaxDynamicSharedMemorySize, SM_64_HF);
    cudaFuncSetAttribute((const void*)flash_attn_kernel, cudaFuncAttributeMaxDynamicSharedMemorySize, FA_SMEM);

    embed_kernel<<<NTOK * C_ / 256, 256>>>(idx, tok_emb, x);

    for (int l = 0; l < L_; l++) {
        // --- attention (routing-critical -> bf16x3; MT=128) ---
        ln_kernel<<<NTOK, 256>>>(x, ln1_g + (size_t)l * C_, ln1_b + (size_t)l * C_, ln);
        mm_mma_kernel<128, 1, false><<<dim3(NTOK / 128, 3 * C_ / 128, 1), 256, SM_128_BF>>>(
            ln, qkv_w + (size_t)l * C_ * 3 * C_, qkv, nullptr, nullptr,
            NTOK, 3 * C_, C_, 0, 0, 0, 0, 0);
        rope_kernel<<<(NTOK * H_ * (HD_ / 2) + 255) / 256, 256>>>(qkv);
        flash_attn_kernel<<<dim3(T_ / 64, B_ * H_), 256, FA_SMEM>>>(qkv, attn);
        mm_mma_kernel<128, 1, false><<<dim3(NTOK / 128, C_ / 128, 1), 256, SM_128_BF>>>(
            attn, proj_w + (size_t)l * C_ * C_, x, nullptr, nullptr,
            NTOK, C_, C_, 0, 0, 0, 0, 1);  // += residual

        // --- MoE (fused ln+gate; w1 gathers token rows directly from ln) ---
        lngate_kernel<<<NTOK, 256>>>(x, ln2_g + (size_t)l * C_, ln2_b + (size_t)l * C_,
                                     gate_w + (size_t)l * C_ * E_, ln, gates, top);
        route_kernel<<<1, 256>>>(top, slot, inv);
        if (l < L_ - 1) {
            mm_mma_kernel<64, 1, true><<<dim3(CAP / 64, FF_ / 128, E_), 256, SM_64_BF>>>(
                ln, w1 + (size_t)l * E_ * C_ * FF_, hbuf, b1 + (size_t)l * E_ * FF_, inv,
                CAP, FF_, C_, 0, (long)C_ * FF_, (long)CAP * FF_, (long)FF_, 2);
            mm_mma_kernel<64, 1, false><<<dim3(CAP / 64, C_ / 128, E_), 256, SM_64_BF>>>(
                hbuf, w2 + (size_t)l * E_ * FF_ * C_, ybuf, b2 + (size_t)l * E_ * C_, nullptr,
                CAP, C_, FF_, (long)CAP * FF_, (long)FF_ * C_, (long)CAP * C_, (long)C_, 3);
        } else {
            mm_mma_kernel<64, 2, true><<<dim3(CAP / 64, FF_ / 128, E_), 256, SM_64_HF>>>(
                ln, w1 + (size_t)l * E_ * C_ * FF_, hbuf, b1 + (size_t)l * E_ * FF_, inv,
                CAP, FF_, C_, 0, (long)C_ * FF_, (long)CAP * FF_, (long)FF_, 2);
            mm_mma_kernel<64, 2, false><<<dim3(CAP / 64, C_ / 128, E_), 256, SM_64_HF>>>(
                hbuf, w2 + (size_t)l * E_ * FF_ * C_, ybuf, b2 + (size_t)l * E_ * C_, nullptr,
                CAP, C_, FF_, (long)CAP * FF_, (long)FF_ * C_, (long)CAP * C_, (long)C_, 3);
        }
        combine_kernel<<<NTOK, 256>>>(ybuf, gates, top, slot, x);
    }

    ln_kernel<<<NTOK, 256>>>(x, lnf_g, lnf_b, ln);
    mm_mma_kernel<128, 2, false><<<dim3(NTOK / 128, V_ / 128, 1), 256, SM_128_HF>>>(
        ln, lm_head, out, nullptr, nullptr, NTOK, V_, C_, 0, 0, 0, 0, 0);
}

// round 16
// speedup vs baseline: 1.2123x; 1.0339x over previous
#include <cuda_runtime.h>
#include <cuda_bf16.h>
#include <cuda_fp16.h>
#include <math.h>
#include <stdint.h>

#define B_   2
#define T_   1024
#define C_   1024
#define H_   16
#define HD_  64
#define L_   2
#define E_   8
#define FF_  4096
#define V_   32000
#define NTOK (B_ * T_)
#define CAP  320

// ---------------- scratch ----------------
__device__ float g_x[NTOK * C_];
__device__ float g_ln[NTOK * C_];
__device__ float g_qkv[NTOK * 3 * C_];
__device__ float g_attn[NTOK * C_];
__device__ float g_gates[NTOK * E_];
__device__ int   g_top[NTOK * 2];
__device__ int   g_slot[NTOK * 2];
__device__ int   g_inv[E_ * CAP];
__device__ float g_hbuf[E_ * CAP * FF_];
__device__ float g_ybuf[E_ * CAP * C_];

// ---------------- helpers ----------------
__device__ __forceinline__ float warp_sum(float v) {
#pragma unroll
    for (int o = 16; o; o >>= 1) v += __shfl_xor_sync(0xffffffffu, v, o);
    return v;
}
__device__ __forceinline__ float gelu_exact(float v) {
    return 0.5f * v * (1.0f + erff(v * 0.70710678118654752f));
}
__device__ __forceinline__ float bf_hi(float v) {
    return __bfloat162float(__float2bfloat16(v));
}
__device__ __forceinline__ uint32_t pack_bf2(float a, float b) {
    uint32_t r;
    asm("cvt.rn.bf16x2.f32 %0, %1, %2;" : "=r"(r) : "f"(b), "f"(a));
    return r;
}
__device__ __forceinline__ uint32_t pack_f16(float a, float b) {
    uint32_t r;
    asm("cvt.rn.f16x2.f32 %0, %1, %2;" : "=r"(r) : "f"(b), "f"(a));
    return r;
}
__device__ __forceinline__ void split_pack(float x0, float x1, uint32_t& hi, uint32_t& lo) {
    float h0 = bf_hi(x0), h1 = bf_hi(x1);
    hi = pack_bf2(h0, h1);
    lo = pack_bf2(x0 - h0, x1 - h1);
}

#define MMA_BF16(accp, a0, a1, a2, a3, b0, b1)                                  \
    asm volatile(                                                               \
        "mma.sync.aligned.m16n8k16.row.col.f32.bf16.bf16.f32 "                  \
        "{%0,%1,%2,%3}, {%4,%5,%6,%7}, {%8,%9}, {%0,%1,%2,%3};"                 \
        : "+f"((accp)[0]), "+f"((accp)[1]), "+f"((accp)[2]), "+f"((accp)[3])    \
        : "r"(a0), "r"(a1), "r"(a2), "r"(a3), "r"(b0), "r"(b1))

#define MMA_F16(accp, a0, a1, a2, a3, b0, b1)                                   \
    asm volatile(                                                               \
        "mma.sync.aligned.m16n8k16.row.col.f32.f16.f16.f32 "                    \
        "{%0,%1,%2,%3}, {%4,%5,%6,%7}, {%8,%9}, {%0,%1,%2,%3};"                 \
        : "+f"((accp)[0]), "+f"((accp)[1]), "+f"((accp)[2]), "+f"((accp)[3])    \
        : "r"(a0), "r"(a1), "r"(a2), "r"(a3), "r"(b0), "r"(b1))

// ======== tensor-core GEMM: pre-split packed smem planes (unchanged, passing) ========
#define PA_ 20
#define PB_ 136

template<int MT, int MODE, bool GATHER>
__global__ void __launch_bounds__(256, MT == 64 ? 2 : 1)
mm_mma_kernel(const float* __restrict__ A, const float* __restrict__ B,
              float* __restrict__ C, const float* __restrict__ bias,
              const int* __restrict__ gidx,
              int Mv, int N, int K,
              long sA, long sB, long sC, long sBias, int ep)
{
    constexpr int MTW   = MT / 32;
    constexpr int AIT   = MT / 32;
    constexpr int APL   = MT * PA_;
    constexpr int BPL   = 16 * PB_;
    constexpr int NPLA  = (MODE == 1) ? 2 : 1;
    constexpr int BUFSZ = NPLA * (APL + BPL);
    extern __shared__ uint32_t smu[];
    int tid = threadIdx.x, lane = tid & 31, wid = tid >> 5;
    int wm = wid & 1, wn = wid >> 1;
    int r_lo = lane >> 2, c_lo = lane & 3;
    int z = blockIdx.z;
    A += (long)z * sA; B += (long)z * sB; C += (long)z * sC;
    const float* bp = bias ? bias + (long)z * sBias : nullptr;
    int m0 = blockIdx.x * MT, n0 = blockIdx.y * 128;

    int grow[AIT];
    if (GATHER) {
#pragma unroll
        for (int it = 0; it < AIT; it++)
            grow[it] = gidx[z * CAP + m0 + ((tid + it * 256) >> 3)];
    }

    float acc[MTW][4][4];
#pragma unroll
    for (int i = 0; i < MTW; i++)
#pragma unroll
        for (int j = 0; j < 4; j++)
#pragma unroll
            for (int k = 0; k < 4; k++) acc[i][j][k] = 0.f;

    float4 pa[AIT];
    float2 pb0[4], pb1[4];

    auto prefetch = [&](int i) {
        int k0 = i << 5;
#pragma unroll
        for (int it = 0; it < AIT; it++) {
            int idx = tid + it * 256;
            int m = idx >> 3, f4 = idx & 7;
            long arow = GATHER ? (long)grow[it] : (long)(m0 + m);
            pa[it] = *(const float4*)(A + (size_t)arow * K + k0 + f4 * 4);
        }
#pragma unroll
        for (int it = 0; it < 4; it++) {
            int idx = tid + it * 256;
            int kp = idx >> 6, n2 = idx & 63;
            const float* bptr = B + (size_t)(k0 + 2 * kp) * N + n0 + 2 * n2;
            pb0[it] = *(const float2*)bptr;
            pb1[it] = *(const float2*)(bptr + N);
        }
    };
    auto cstore = [&](int s) {
        uint32_t* base = smu + s * BUFSZ;
        uint32_t* Ah = base;
        uint32_t* Al = base + APL;
        uint32_t* Bh = base + NPLA * APL;
        uint32_t* Bl = Bh + BPL;
#pragma unroll
        for (int it = 0; it < AIT; it++) {
            int idx = tid + it * 256;
            int m = idx >> 3, f4 = idx & 7;
            float4 v = pa[it];
            if constexpr (MODE == 1) {
                uint32_t h0, l0, h1, l1;
                split_pack(v.x, v.y, h0, l0);
                split_pack(v.z, v.w, h1, l1);
                *(uint2*)(Ah + m * PA_ + 2 * f4) = make_uint2(h0, h1);
                *(uint2*)(Al + m * PA_ + 2 * f4) = make_uint2(l0, l1);
            } else {
                *(uint2*)(Ah + m * PA_ + 2 * f4) =
                    make_uint2(pack_f16(v.x, v.y), pack_f16(v.z, v.w));
            }
        }
#pragma unroll
        for (int it = 0; it < 4; it++) {
            int idx = tid + it * 256;
            int kp = idx >> 6, n2 = idx & 63;
            float2 f0 = pb0[it], f1 = pb1[it];
            if constexpr (MODE == 1) {
                uint32_t h0, l0, h1, l1;
                split_pack(f0.x, f1.x, h0, l0);
                split_pack(f0.y, f1.y, h1, l1);
                *(uint2*)(Bh + kp * PB_ + 2 * n2) = make_uint2(h0, h1);
                *(uint2*)(Bl + kp * PB_ + 2 * n2) = make_uint2(l0, l1);
            } else {
                *(uint2*)(Bh + kp * PB_ + 2 * n2) =
                    make_uint2(pack_f16(f0.x, f1.x), pack_f16(f0.y, f1.y));
            }
        }
    };

    int nch = K >> 5;
    prefetch(0);
    cstore(0);
    __syncthreads();
    for (int i = 0; i < nch; i++) {
        if (i + 1 < nch) prefetch(i + 1);
        {
            uint32_t* base = smu + (i & 1) * BUFSZ;
            uint32_t* Ah = base;
            uint32_t* Al = base + APL;
            uint32_t* Bh = base + NPLA * APL;
            uint32_t* Bl = Bh + BPL;
#pragma unroll
            for (int ks = 0; ks < 2; ks++) {
                int kq = ks * 8 + c_lo;
                if constexpr (MODE == 1) {
                    uint32_t ah[MTW][4], al[MTW][4], bh[4][2], bl[4][2];
#pragma unroll
                    for (int mt = 0; mt < MTW; mt++) {
                        int ro = (wm * (MT / 2) + mt * 16 + r_lo) * PA_ + kq;
                        ah[mt][0] = Ah[ro];
                        ah[mt][1] = Ah[ro + 8 * PA_];
                        ah[mt][2] = Ah[ro + 4];
                        ah[mt][3] = Ah[ro + 8 * PA_ + 4];
                        al[mt][0] = Al[ro];
                        al[mt][1] = Al[ro + 8 * PA_];
                        al[mt][2] = Al[ro + 4];
                        al[mt][3] = Al[ro + 8 * PA_ + 4];
                    }
#pragma unroll
                    for (int nt = 0; nt < 4; nt++) {
                        int bo = kq * PB_ + wn * 32 + nt * 8 + r_lo;
                        bh[nt][0] = Bh[bo];
                        bh[nt][1] = Bh[bo + 4 * PB_];
                        bl[nt][0] = Bl[bo];
                        bl[nt][1] = Bl[bo + 4 * PB_];
                    }
#pragma unroll
                    for (int mt = 0; mt < MTW; mt++)
#pragma unroll
                        for (int nt = 0; nt < 4; nt++) {
                            MMA_BF16(acc[mt][nt], ah[mt][0], ah[mt][1], ah[mt][2], ah[mt][3],
                                     bh[nt][0], bh[nt][1]);
                            MMA_BF16(acc[mt][nt], ah[mt][0], ah[mt][1], ah[mt][2], ah[mt][3],
                                     bl[nt][0], bl[nt][1]);
                            MMA_BF16(acc[mt][nt], al[mt][0], al[mt][1], al[mt][2], al[mt][3],
                                     bh[nt][0], bh[nt][1]);
                        }
                } else {
                    uint32_t ah[MTW][4], bh[4][2];
#pragma unroll
                    for (int mt = 0; mt < MTW; mt++) {
                        int ro = (wm * (MT / 2) + mt * 16 + r_lo) * PA_ + kq;
                        ah[mt][0] = Ah[ro];
                        ah[mt][1] = Ah[ro + 8 * PA_];
                        ah[mt][2] = Ah[ro + 4];
                        ah[mt][3] = Ah[ro + 8 * PA_ + 4];
                    }
#pragma unroll
                    for (int nt = 0; nt < 4; nt++) {
                        int bo = kq * PB_ + wn * 32 + nt * 8 + r_lo;
                        bh[nt][0] = Bh[bo];
                        bh[nt][1] = Bh[bo + 4 * PB_];
                    }
#pragma unroll
                    for (int mt = 0; mt < MTW; mt++)
#pragma unroll
                        for (int nt = 0; nt < 4; nt++)
                            MMA_F16(acc[mt][nt], ah[mt][0], ah[mt][1], ah[mt][2], ah[mt][3],
                                    bh[nt][0], bh[nt][1]);
                }
            }
        }
        __syncthreads();
        if (i + 1 < nch) {
            cstore((i + 1) & 1);
            __syncthreads();
        }
    }

    int rbase = m0 + wm * (MT / 2) + (lane >> 2);
    int cbase = n0 + wn * 32 + (lane & 3) * 2;
#pragma unroll
    for (int mt = 0; mt < MTW; mt++) {
#pragma unroll
        for (int half = 0; half < 2; half++) {
            int row = rbase + mt * 16 + half * 8;
            if (row >= Mv) continue;
#pragma unroll
            for (int nt = 0; nt < 4; nt++) {
                int col = cbase + nt * 8;
                float x0 = acc[mt][nt][half * 2 + 0];
                float x1 = acc[mt][nt][half * 2 + 1];
                if (ep == 2)      { x0 = gelu_exact(x0 + bp[col]); x1 = gelu_exact(x1 + bp[col + 1]); }
                else if (ep == 3) { x0 += bp[col]; x1 += bp[col + 1]; }
                float* cp = C + (size_t)row * N + col;
                if (ep == 1) { x0 += cp[0]; x1 += cp[1]; }
                float2 o; o.x = x0; o.y = x1;
                *(float2*)cp = o;
            }
        }
    }
}
#define SMSZ(MT, NPLA) (2 * (NPLA) * ((MT) * PA_ + 16 * PB_) * 4)
#define SM_128_BF SMSZ(128, 2)
#define SM_128_HF SMSZ(128, 1)
#define SM_64_BF  SMSZ(64, 2)
#define SM_64_HF  SMSZ(64, 1)

// ---------------- embedding gather ----------------
__global__ void embed_kernel(const int* __restrict__ idx, const float* __restrict__ emb,
                             float* __restrict__ x) {
    int i = blockIdx.x * 256 + threadIdx.x;
    int n = i >> 10, c = i & 1023;
    x[i] = emb[(size_t)idx[n] * C_ + c];
}

// ---------------- layernorm ----------------
__global__ void ln_kernel(const float* __restrict__ x, const float* __restrict__ g,
                          const float* __restrict__ b, float* __restrict__ out) {
    int row = blockIdx.x;
    const float* xr = x + (size_t)row * C_;
    float s = 0.f, s2 = 0.f;
    for (int c = threadIdx.x; c < C_; c += 256) { float v = xr[c]; s += v; s2 += v * v; }
    __shared__ float sh1[8], sh2[8], shm[2];
    int lane = threadIdx.x & 31, w = threadIdx.x >> 5;
    s = warp_sum(s); s2 = warp_sum(s2);
    if (!lane) { sh1[w] = s; sh2[w] = s2; }
    __syncthreads();
    if (threadIdx.x == 0) {
        float S = 0.f, S2 = 0.f;
        for (int i = 0; i < 8; i++) { S += sh1[i]; S2 += sh2[i]; }
        float mean = S * (1.0f / C_);
        float var  = S2 * (1.0f / C_) - mean * mean;
        shm[0] = mean; shm[1] = rsqrtf(var + 1e-5f);
    }
    __syncthreads();
    float mean = shm[0], inv = shm[1];
    float* orow = out + (size_t)row * C_;
    for (int c = threadIdx.x; c < C_; c += 256)
        orow[c] = (xr[c] - mean) * inv * g[c] + b[c];
}

// ---------------- fused layernorm + gate ----------------
__global__ void lngate_kernel(const float* __restrict__ x, const float* __restrict__ g,
                              const float* __restrict__ b, const float* __restrict__ gw,
                              float* __restrict__ out, float* __restrict__ gates,
                              int* __restrict__ top) {
    int row = blockIdx.x;
    const float* xr = x + (size_t)row * C_;
    __shared__ float sh1[8], sh2[8], shm[2], lnrow[C_], sl[E_];
    int lane = threadIdx.x & 31, w = threadIdx.x >> 5;
    float s = 0.f, s2 = 0.f;
    for (int c = threadIdx.x; c < C_; c += 256) { float v = xr[c]; s += v; s2 += v * v; }
    s = warp_sum(s); s2 = warp_sum(s2);
    if (!lane) { sh1[w] = s; sh2[w] = s2; }
    __syncthreads();
    if (threadIdx.x == 0) {
        float S = 0.f, S2 = 0.f;
        for (int i = 0; i < 8; i++) { S += sh1[i]; S2 += sh2[i]; }
        float mean = S * (1.0f / C_);
        float var  = S2 * (1.0f / C_) - mean * mean;
        shm[0] = mean; shm[1] = rsqrtf(var + 1e-5f);
    }
    __syncthreads();
    float mean = shm[0], inv = shm[1];
    float* orow = out + (size_t)row * C_;
    for (int c = threadIdx.x; c < C_; c += 256) {
        float v = (xr[c] - mean) * inv * g[c] + b[c];
        lnrow[c] = v;
        orow[c] = v;
    }
    __syncthreads();
    float acc = 0.f;
    for (int c = lane; c < C_; c += 32) acc += lnrow[c] * gw[(size_t)c * E_ + w];
    acc = warp_sum(acc);
    if (!lane) sl[w] = acc;
    __syncthreads();
    if (threadIdx.x == 0) {
        float p[E_];
        float m = sl[0];
        for (int e = 1; e < E_; e++) m = fmaxf(m, sl[e]);
        float ssum = 0.f;
        for (int e = 0; e < E_; e++) { p[e] = expf(sl[e] - m); ssum += p[e]; }
        float invs = 1.0f / ssum;
        for (int e = 0; e < E_; e++) { p[e] *= invs; gates[(size_t)row * E_ + e] = p[e]; }
        int i0 = 0;
        for (int e = 1; e < E_; e++) if (p[e] > p[i0]) i0 = e;
        int i1 = -1;
        for (int e = 0; e < E_; e++) {
            if (e == i0) continue;
            if (i1 < 0 || p[e] > p[i1]) i1 = e;
        }
        top[2 * row] = i0; top[2 * row + 1] = i1;
    }
}

// ---------------- RoPE ----------------
__global__ void rope_kernel(float* __restrict__ qkv) {
    int i = blockIdx.x * 256 + threadIdx.x;
    if (i >= NTOK * H_ * (HD_ / 2)) return;
    int j = i & 31;
    int h = (i >> 5) & 15;
    int n = i >> 9;
    int t = n & (T_ - 1);
    float e = (float)(2 * j) / (float)HD_;
    float invf = 1.0f / powf(10000.0f, e);
    float ang = (float)t * invf;
    float s = sinf(ang), c = cosf(ang);
    float* base = qkv + (size_t)n * (3 * C_) + h * (3 * HD_);
    float q1 = base[j],      q2 = base[j + 32];
    base[j]      = q1 * c - q2 * s;
    base[j + 32] = q1 * s + q2 * c;
    float k1 = base[64 + j], k2 = base[64 + j + 32];
    base[64 + j]      = k1 * c - k2 * s;
    base[64 + j + 32] = k1 * s + k2 * c;
}

// ---------------- tensor-core flash attention: pre-split packed planes ----------------
// Q split once before the kb loop; K/V split at tile load; P split at fragment store.
// Q/K/P planes: [64 rows][36 u32] (kpair along d or token; banks 4r+c distinct).
// V planes: [32 kpair_tok][72 u32] (banks 8c+r distinct).
#define FQP 36
#define FVP 72
#define PL_SZ (64 * FQP)            // 2304 u32 (V plane 32*72 = 2304 as well)
#define FO_QH 0
#define FO_QL (1 * PL_SZ)
#define FO_KH (2 * PL_SZ)
#define FO_KL (3 * PL_SZ)
#define FO_VH (4 * PL_SZ)
#define FO_VL (5 * PL_SZ)
#define FO_PH (6 * PL_SZ)
#define FO_PL (7 * PL_SZ)
#define FO_ST (8 * PL_SZ)           // float stats region
#define FA_SMEM ((FO_ST + 448) * 4)

__global__ void __launch_bounds__(256, 1)
flash_attn_kernel(const float* __restrict__ qkv, float* __restrict__ out) {
    extern __shared__ uint32_t fsu[];
    uint32_t* QH = fsu + FO_QH; uint32_t* QL = fsu + FO_QL;
    uint32_t* KH = fsu + FO_KH; uint32_t* KL = fsu + FO_KL;
    uint32_t* VH = fsu + FO_VH; uint32_t* VL = fsu + FO_VL;
    uint32_t* PH = fsu + FO_PH; uint32_t* PL = fsu + FO_PL;
    float* st = (float*)(fsu + FO_ST);
    float* Wmax = st;          // [2][64]
    float* Wsum = st + 128;    // [2][64]
    float* Mrow = st + 256;
    float* Lrow = st + 320;
    float* Arow = st + 384;
    int bh = blockIdx.y; int b = bh >> 4, h = bh & 15;
    int qb = (int)gridDim.x - 1 - (int)blockIdx.x;
    int q0 = qb * 64;
    int tid = threadIdx.x, lane = tid & 31, wid = tid >> 5;
    int wm = wid & 3, wn = wid >> 2;
    int r_lo = lane >> 2, c_lo = lane & 3;
    int row0 = wm * 16 + r_lo;

    // Q: load + split ONCE
    const float* qbase = qkv + (size_t)(b * T_ + q0) * (3 * C_) + h * (3 * HD_);
#pragma unroll
    for (int r = 0; r < 4; r++) {
        int idx = tid + r * 256;
        int tok = idx >> 4, kp = (idx & 15) * 2;       // kpair base (2 kpairs per float4)
        float4 v = *(const float4*)(qbase + (size_t)tok * (3 * C_) + 2 * kp);
        uint32_t h0, l0, h1, l1;
        split_pack(v.x, v.y, h0, l0);
        split_pack(v.z, v.w, h1, l1);
        *(uint2*)(QH + tok * FQP + kp) = make_uint2(h0, h1);
        *(uint2*)(QL + tok * FQP + kp) = make_uint2(l0, l1);
    }
    if (tid < 64) { Mrow[tid] = -1e30f; Lrow[tid] = 0.f; }

    float oacc[4][4];
#pragma unroll
    for (int nt = 0; nt < 4; nt++)
#pragma unroll
        for (int q = 0; q < 4; q++) oacc[nt][q] = 0.f;

    for (int kb = 0; kb <= qb; kb++) {
        int k0 = kb * 64;
        __syncthreads();   // prior iter's plane reads complete (and Q ready, iter 0)
        const float* kbase = qkv + (size_t)(b * T_ + k0) * (3 * C_) + h * (3 * HD_) + HD_;
        const float* vbase = kbase + HD_;
        // K: split at load, layout [tok][kpair_d]
#pragma unroll
        for (int r = 0; r < 4; r++) {
            int idx = tid + r * 256;
            int tok = idx >> 4, kp = (idx & 15) * 2;
            float4 v = *(const float4*)(kbase + (size_t)tok * (3 * C_) + 2 * kp);
            uint32_t h0, l0, h1, l1;
            split_pack(v.x, v.y, h0, l0);
            split_pack(v.z, v.w, h1, l1);
            *(uint2*)(KH + tok * FQP + kp) = make_uint2(h0, h1);
            *(uint2*)(KL + tok * FQP + kp) = make_uint2(l0, l1);
        }
        // V: split at load, layout [kpair_tok][d]
#pragma unroll
        for (int r = 0; r < 2; r++) {
            int task = tid + r * 256;                   // 512 tasks
            int kp = task >> 4, db = (task & 15) * 4;
            const float* v0p = vbase + (size_t)(2 * kp) * (3 * C_) + db;
            float4 v0 = *(const float4*)v0p;
            float4 v1 = *(const float4*)(v0p + 3 * C_);
            uint32_t hh[4], ll[4];
            split_pack(v0.x, v1.x, hh[0], ll[0]);
            split_pack(v0.y, v1.y, hh[1], ll[1]);
            split_pack(v0.z, v1.z, hh[2], ll[2]);
            split_pack(v0.w, v1.w, hh[3], ll[3]);
            *(uint4*)(VH + kp * FVP + db) = make_uint4(hh[0], hh[1], hh[2], hh[3]);
            *(uint4*)(VL + kp * FVP + db) = make_uint4(ll[0], ll[1], ll[2], ll[3]);
        }
        __syncthreads();

        // ---- S = Q @ K^T (bf16x3, pure LDS+mma) ----
        float sacc[4][4];
#pragma unroll
        for (int nt = 0; nt < 4; nt++)
#pragma unroll
            for (int q = 0; q < 4; q++) sacc[nt][q] = 0.f;
#pragma unroll
        for (int sl = 0; sl < 4; sl++) {
            int kq = sl * 8 + c_lo;
            int ro = (wm * 16 + r_lo) * FQP + kq;
            uint32_t ah[4], al[4];
            ah[0] = QH[ro];             al[0] = QL[ro];
            ah[1] = QH[ro + 8 * FQP];   al[1] = QL[ro + 8 * FQP];
            ah[2] = QH[ro + 4];         al[2] = QL[ro + 4];
            ah[3] = QH[ro + 8 * FQP + 4]; al[3] = QL[ro + 8 * FQP + 4];
#pragma unroll
            for (int nt = 0; nt < 4; nt++) {
                int bo = (wn * 32 + nt * 8 + r_lo) * FQP + kq;
                uint32_t bh0 = KH[bo], bh1 = KH[bo + 4];
                uint32_t bl0 = KL[bo], bl1 = KL[bo + 4];
                MMA_BF16(sacc[nt], ah[0], ah[1], ah[2], ah[3], bh0, bh1);
                MMA_BF16(sacc[nt], ah[0], ah[1], ah[2], ah[3], bl0, bl1);
                MMA_BF16(sacc[nt], al[0], al[1], al[2], al[3], bh0, bh1);
            }
        }
        bool diag = (kb == qb);
#pragma unroll
        for (int nt = 0; nt < 4; nt++)
#pragma unroll
            for (int q = 0; q < 4; q++) {
                int rloc = (q >= 2) ? row0 + 8 : row0;
                int cloc = wn * 32 + nt * 8 + 2 * c_lo + (q & 1);
                float v = sacc[nt][q] * 0.125f;
                if (diag && cloc > rloc) v = -1e30f;
                sacc[nt][q] = v;
            }
        float rm0 = -1e30f, rm1 = -1e30f;
#pragma unroll
        for (int nt = 0; nt < 4; nt++) {
            rm0 = fmaxf(rm0, fmaxf(sacc[nt][0], sacc[nt][1]));
            rm1 = fmaxf(rm1, fmaxf(sacc[nt][2], sacc[nt][3]));
        }
        rm0 = fmaxf(rm0, __shfl_xor_sync(0xffffffffu, rm0, 1));
        rm0 = fmaxf(rm0, __shfl_xor_sync(0xffffffffu, rm0, 2));
        rm1 = fmaxf(rm1, __shfl_xor_sync(0xffffffffu, rm1, 1));
        rm1 = fmaxf(rm1, __shfl_xor_sync(0xffffffffu, rm1, 2));
        if (c_lo == 0) {
            Wmax[wn * 64 + row0] = rm0;
            Wmax[wn * 64 + row0 + 8] = rm1;
        }
        __syncthreads();
        float mn0 = fmaxf(Mrow[row0],     fmaxf(Wmax[row0],     Wmax[64 + row0]));
        float mn1 = fmaxf(Mrow[row0 + 8], fmaxf(Wmax[row0 + 8], Wmax[64 + row0 + 8]));
        float rs0 = 0.f, rs1 = 0.f;
#pragma unroll
        for (int nt = 0; nt < 4; nt++) {
            float p0 = expf(sacc[nt][0] - mn0);
            float p1 = expf(sacc[nt][1] - mn0);
            float p2 = expf(sacc[nt][2] - mn1);
            float p3 = expf(sacc[nt][3] - mn1);
            rs0 += p0 + p1; rs1 += p2 + p3;
            int kpc = wn * 16 + nt * 4 + c_lo;          // kpair (token pair) column
            uint32_t hh, ll;
            split_pack(p0, p1, hh, ll);
            PH[(wm * 16 + r_lo) * FQP + kpc] = hh;
            PL[(wm * 16 + r_lo) * FQP + kpc] = ll;
            split_pack(p2, p3, hh, ll);
            PH[(wm * 16 + r_lo + 8) * FQP + kpc] = hh;
            PL[(wm * 16 + r_lo + 8) * FQP + kpc] = ll;
        }
        rs0 += __shfl_xor_sync(0xffffffffu, rs0, 1);
        rs0 += __shfl_xor_sync(0xffffffffu, rs0, 2);
        rs1 += __shfl_xor_sync(0xffffffffu, rs1, 1);
        rs1 += __shfl_xor_sync(0xffffffffu, rs1, 2);
        if (c_lo == 0) {
            Wsum[wn * 64 + row0] = rs0;
            Wsum[wn * 64 + row0 + 8] = rs1;
        }
        __syncthreads();
        if (tid < 64) {
            int r = tid;
            float mold = Mrow[r];
            float mn = fmaxf(mold, fmaxf(Wmax[r], Wmax[64 + r]));
            float a = expf(mold - mn);
            Arow[r] = a;
            Lrow[r] = Lrow[r] * a + Wsum[r] + Wsum[64 + r];
            Mrow[r] = mn;
        }
        __syncthreads();
        float a0 = Arow[row0], a1 = Arow[row0 + 8];
#pragma unroll
        for (int nt = 0; nt < 4; nt++) {
            oacc[nt][0] *= a0; oacc[nt][1] *= a0;
            oacc[nt][2] *= a1; oacc[nt][3] *= a1;
        }
        // ---- O += P @ V (bf16x3, pure LDS+mma) ----
#pragma unroll
        for (int sl = 0; sl < 4; sl++) {
            int kq = sl * 8 + c_lo;                     // kpair over tokens
            int ro = (wm * 16 + r_lo) * FQP + kq;
            uint32_t ah[4], al[4];
            ah[0] = PH[ro];             al[0] = PL[ro];
            ah[1] = PH[ro + 8 * FQP];   al[1] = PL[ro + 8 * FQP];
            ah[2] = PH[ro + 4];         al[2] = PL[ro + 4];
            ah[3] = PH[ro + 8 * FQP + 4]; al[3] = PL[ro + 8 * FQP + 4];
#pragma unroll
            for (int nt = 0; nt < 4; nt++) {
                int bo = kq * FVP + wn * 32 + nt * 8 + r_lo;
                uint32_t bh0 = VH[bo], bh1 = VH[bo + 4 * FVP];
                uint32_t bl0 = VL[bo], bl1 = VL[bo + 4 * FVP];
                MMA_BF16(oacc[nt], ah[0], ah[1], ah[2], ah[3], bh0, bh1);
                MMA_BF16(oacc[nt], ah[0], ah[1], ah[2], ah[3], bl0, bl1);
                MMA_BF16(oacc[nt], al[0], al[1], al[2], al[3], bh0, bh1);
            }
        }
    }

    float l0 = 1.0f / Lrow[row0], l1 = 1.0f / Lrow[row0 + 8];
#pragma unroll
    for (int nt = 0; nt < 4; nt++) {
        int col = wn * 32 + nt * 8 + 2 * c_lo;
        float2 v0; v0.x = oacc[nt][0] * l0; v0.y = oacc[nt][1] * l0;
        float2 v1; v1.x = oacc[nt][2] * l1; v1.y = oacc[nt][3] * l1;
        *(float2*)(out + (size_t)(b * T_ + q0 + row0) * C_ + h * HD_ + col)     = v0;
        *(float2*)(out + (size_t)(b * T_ + q0 + row0 + 8) * C_ + h * HD_ + col) = v1;
    }
}

// ---------------- routing ----------------
__global__ void route_kernel(const int* __restrict__ top, int* __restrict__ slot,
                             int* __restrict__ inv) {
    int e = threadIdx.x >> 5, lane = threadIdx.x & 31;
    for (int i = lane; i < CAP; i += 32) inv[e * CAP + i] = 0;
    int cnt = 0;
    for (int base = 0; base < NTOK; base += 32) {
        int n = base + lane;
        int t0 = top[2 * n], t1 = top[2 * n + 1];
        bool m = (t0 == e) || (t1 == e);
        unsigned ball = __ballot_sync(0xffffffffu, m);
        if (m) {
            int pos = cnt + __popc(ball & ((1u << lane) - 1));
            int s = (pos < CAP) ? pos : -1;
            if (s >= 0) inv[e * CAP + s] = n;
            if (t0 == e) slot[2 * n] = s; else slot[2 * n + 1] = s;
        }
        cnt += __popc(ball);
    }
}

// ---------------- combine + residual ----------------
__global__ void combine_kernel(const float* __restrict__ y, const float* __restrict__ gates,
                               const int* __restrict__ top, const int* __restrict__ slot,
                               float* __restrict__ x) {
    int n = blockIdx.x;
    int e0 = top[2 * n], e1 = top[2 * n + 1];
    int s0 = slot[2 * n], s1 = slot[2 * n + 1];
    float w0 = (s0 >= 0) ? gates[(size_t)n * E_ + e0] : 0.f;
    float w1 = (s1 >= 0) ? gates[(size_t)n * E_ + e1] : 0.f;
    const float* y0 = y + ((size_t)e0 * CAP + (s0 >= 0 ? s0 : 0)) * C_;
    const float* y1 = y + ((size_t)e1 * CAP + (s1 >= 0 ? s1 : 0)) * C_;
    float* xr = x + (size_t)n * C_;
    for (int c = threadIdx.x; c < C_; c += 256)
        xr[c] += w0 * y0[c] + w1 * y1[c];
}

// ---------------- launch ----------------
extern "C" void kernel_launch(void* const* d_in, const int* in_sizes, int n_in,
                              void* d_out, int out_size) {
    const int*   idx     = (const int*)  d_in[0];
    const float* tok_emb = (const float*)d_in[1];
    const float* ln1_g   = (const float*)d_in[2];
    const float* ln1_b   = (const float*)d_in[3];
    const float* qkv_w   = (const float*)d_in[4];
    const float* proj_w  = (const float*)d_in[5];
    const float* ln2_g   = (const float*)d_in[6];
    const float* ln2_b   = (const float*)d_in[7];
    const float* gate_w  = (const float*)d_in[8];
    const float* w1      = (const float*)d_in[9];
    const float* b1      = (const float*)d_in[10];
    const float* w2      = (const float*)d_in[11];
    const float* b2      = (const float*)d_in[12];
    const float* lnf_g   = (const float*)d_in[13];
    const float* lnf_b   = (const float*)d_in[14];
    const float* lm_head = (const float*)d_in[15];
    float* out = (float*)d_out;

    float *x, *ln, *qkv, *attn, *gates, *hbuf, *ybuf;
    int *top, *slot, *inv;
    cudaGetSymbolAddress((void**)&x,     g_x);
    cudaGetSymbolAddress((void**)&ln,    g_ln);
    cudaGetSymbolAddress((void**)&qkv,   g_qkv);
    cudaGetSymbolAddress((void**)&attn,  g_attn);
    cudaGetSymbolAddress((void**)&gates, g_gates);
    cudaGetSymbolAddress((void**)&top,   g_top);
    cudaGetSymbolAddress((void**)&slot,  g_slot);
    cudaGetSymbolAddress((void**)&inv,   g_inv);
    cudaGetSymbolAddress((void**)&hbuf,  g_hbuf);
    cudaGetSymbolAddress((void**)&ybuf,  g_ybuf);

    cudaFuncSetAttribute((const void*)mm_mma_kernel<128, 1, false>, cudaFuncAttributeMaxDynamicSharedMemorySize, SM_128_BF);
    cudaFuncSetAttribute((const void*)mm_mma_kernel<128, 2, false>, cudaFuncAttributeMaxDynamicSharedMemorySize, SM_128_HF);
    cudaFuncSetAttribute((const void*)mm_mma_kernel<64, 1, false>,  cudaFuncAttributeMaxDynamicSharedMemorySize, SM_64_BF);
    cudaFuncSetAttribute((const void*)mm_mma_kernel<64, 2, false>,  cudaFuncAttributeMaxDynamicSharedMemorySize, SM_64_HF);
    cudaFuncSetAttribute((const void*)mm_mma_kernel<64, 1, true>,   cudaFuncAttributeMaxDynamicSharedMemorySize, SM_64_BF);
    cudaFuncSetAttribute((const void*)mm_mma_kernel<64, 2, true>,   cudaFuncAttributeMaxDynamicSharedMemorySize, SM_64_HF);
    cudaFuncSetAttribute((const void*)flash_attn_kernel, cudaFuncAttributeMaxDynamicSharedMemorySize, FA_SMEM);

    embed_kernel<<<NTOK * C_ / 256, 256>>>(idx, tok_emb, x);

    for (int l = 0; l < L_; l++) {
        // --- attention (routing-critical -> bf16x3; MT=128) ---
        ln_kernel<<<NTOK, 256>>>(x, ln1_g + (size_t)l * C_, ln1_b + (size_t)l * C_, ln);
        mm_mma_kernel<128, 1, false><<<dim3(NTOK / 128, 3 * C_ / 128, 1), 256, SM_128_BF>>>(
            ln, qkv_w + (size_t)l * C_ * 3 * C_, qkv, nullptr, nullptr,
            NTOK, 3 * C_, C_, 0, 0, 0, 0, 0);
        rope_kernel<<<(NTOK * H_ * (HD_ / 2) + 255) / 256, 256>>>(qkv);
        flash_attn_kernel<<<dim3(T_ / 64, B_ * H_), 256, FA_SMEM>>>(qkv, attn);
        mm_mma_kernel<128, 1, false><<<dim3(NTOK / 128, C_ / 128, 1), 256, SM_128_BF>>>(
            attn, proj_w + (size_t)l * C_ * C_, x, nullptr, nullptr,
            NTOK, C_, C_, 0, 0, 0, 0, 1);  // += residual

        // --- MoE ---
        lngate_kernel<<<NTOK, 256>>>(x, ln2_g + (size_t)l * C_, ln2_b + (size_t)l * C_,
                                     gate_w + (size_t)l * C_ * E_, ln, gates, top);
        route_kernel<<<1, 256>>>(top, slot, inv);
        if (l < L_ - 1) {
            mm_mma_kernel<64, 1, true><<<dim3(CAP / 64, FF_ / 128, E_), 256, SM_64_BF>>>(
                ln, w1 + (size_t)l * E_ * C_ * FF_, hbuf, b1 + (size_t)l * E_ * FF_, inv,
                CAP, FF_, C_, 0, (long)C_ * FF_, (long)CAP * FF_, (long)FF_, 2);
            mm_mma_kernel<64, 1, false><<<dim3(CAP / 64, C_ / 128, E_), 256, SM_64_BF>>>(
                hbuf, w2 + (size_t)l * E_ * FF_ * C_, ybuf, b2 + (size_t)l * E_ * C_, nullptr,
                CAP, C_, FF_, (long)CAP * FF_, (long)FF_ * C_, (long)CAP * C_, (long)C_, 3);
        } else {
            mm_mma_kernel<64, 2, true><<<dim3(CAP / 64, FF_ / 128, E_), 256, SM_64_HF>>>(
                ln, w1 + (size_t)l * E_ * C_ * FF_, hbuf, b1 + (size_t)l * E_ * FF_, inv,
                CAP, FF_, C_, 0, (long)C_ * FF_, (long)CAP * FF_, (long)FF_, 2);
            mm_mma_kernel<64, 2, false><<<dim3(CAP / 64, C_ / 128, E_), 256, SM_64_HF>>>(
                hbuf, w2 + (size_t)l * E_ * FF_ * C_, ybuf, b2 + (size_t)l * E_ * C_, nullptr,
                CAP, C_, FF_, (long)CAP * FF_, (long)FF_ * C_, (long)CAP * C_, (long)C_, 3);
        }
        combine_kernel<<<NTOK, 256>>>(ybuf, gates, top, slot, x);
    }

    ln_kernel<<<NTOK, 256>>>(x, lnf_g, lnf_b, ln);
    mm_mma_kernel<128, 2, false><<<dim3(NTOK / 128, V_ / 128, 1), 256, SM_128_HF>>>(
        ln, lm_head, out, nullptr, nullptr, NTOK, V_, C_, 0, 0, 0, 0, 0);
}